// round 7
// baseline (speedup 1.0000x reference)
#include <cuda_runtime.h>
#include <math_constants.h>

#define BB     8
#define NN     4096
#define BNN    (BB * NN)
#define CIN    128
#define EOUT   5
#define SEMOUT 13
#define KSEL   30
#define QCAP   8
#define TP     32
#define XPAD   36
#define WPAD   129
#define NSLICE 4
#define SLEN   (NN / NSLICE)
#define KQT    128            // query-threads per knn block

#define FINF  __int_as_float(0x7f800000)
#define FNINF __int_as_float(0xff800000)

// ---------------- scratch (static __device__, no runtime alloc) ----------------
__device__ float  g_fsemT[BNN * CIN];            // 16MB [b][n][c]
__device__ float4 g_tA[BNN];                     // (e0,e1,e2,e3)
__device__ float2 g_tB[BNN];                     // (e4, r=||e||^2)
__device__ int    g_nn[BNN * KSEL];              // final neighbor indices
__device__ float  g_pd[NSLICE * KSEL * BNN];     // partial scores, [sl*30+j][bq]
__device__ int    g_pi[NSLICE * KSEL * BNN];     // partial indices, [sl*30+j][bq]

// ================================================================
// Phase 1 (byte-identical logic to R4/R5)
// ================================================================
__global__ void __launch_bounds__(128, 4) phase1_kernel(
    const float* __restrict__ f_sem, const float* __restrict__ f_ins,
    const float* __restrict__ W_adapt, const float* __restrict__ b_adapt,
    const float* __restrict__ gamma, const float* __restrict__ beta,
    const float* __restrict__ W_ins, const float* __restrict__ b_ins,
    float* __restrict__ e_out)
{
    extern __shared__ float sm1[];
    float* Ws = sm1;                      // 32*129
    float* Xs = sm1 + 32 * WPAD;          // 128*36 (reused as Ys)
    float* Wi = Xs + 128 * XPAD;          // 5*128 + 8

    const int tid = threadIdx.x;
    const int blk = blockIdx.x;
    const int b   = blk >> 7;
    const int n0  = (blk & 127) * TP;

    for (int i = tid; i < EOUT * 128; i += 128) Wi[i] = W_ins[i];
    if (tid < EOUT) Wi[EOUT * 128 + tid] = b_ins[tid];

    const float* fs = f_sem + ((size_t)b * CIN) * NN + n0;
    for (int i = tid; i < 128 * TP; i += 128) {
        int c = i >> 5, p = i & 31;
        Xs[c * XPAD + p] = fs[(size_t)c * NN + p];
    }
    __syncthreads();

    {
        float* dst = g_fsemT + ((size_t)(b * NN + n0)) * CIN + tid;
        #pragma unroll 4
        for (int p = 0; p < TP; p++)
            dst[(size_t)p * CIN] = Xs[tid * XPAD + p];
    }

    float acc[TP];
    #pragma unroll
    for (int p = 0; p < TP; p++) acc[p] = 0.f;

    #pragma unroll 1
    for (int ch = 0; ch < 4; ch++) {
        if (ch) __syncthreads();
        for (int i = tid; i < 32 * 128; i += 128) {
            int o  = i >> 5;
            int cc = i & 31;
            Ws[cc * WPAD + o] = W_adapt[o * 128 + ch * 32 + cc];
        }
        __syncthreads();

        #pragma unroll 4
        for (int cc = 0; cc < 32; cc++) {
            float w = Ws[cc * WPAD + tid];
            const float4* xr = (const float4*)(Xs + (ch * 32 + cc) * XPAD);
            #pragma unroll
            for (int p4 = 0; p4 < TP / 4; p4++) {
                float4 x = xr[p4];
                acc[4 * p4 + 0] = fmaf(w, x.x, acc[4 * p4 + 0]);
                acc[4 * p4 + 1] = fmaf(w, x.y, acc[4 * p4 + 1]);
                acc[4 * p4 + 2] = fmaf(w, x.z, acc[4 * p4 + 2]);
                acc[4 * p4 + 3] = fmaf(w, x.w, acc[4 * p4 + 3]);
            }
        }
    }

    const float g  = gamma[tid];
    const float bb = fmaf(g, b_adapt[tid], beta[tid]);
    const float* fi = f_ins + ((size_t)(b * CIN + tid)) * NN + n0;
    float y[TP];
    #pragma unroll
    for (int p = 0; p < TP; p++) {
        float a = fmaxf(fmaf(g, acc[p], bb), 0.f);
        y[p] = fi[p] + a;
    }
    __syncthreads();
    #pragma unroll
    for (int p = 0; p < TP; p++) Xs[tid * XPAD + p] = y[p];
    __syncthreads();

    if (tid < TP) {
        const int p = tid;
        float e[EOUT];
        #pragma unroll
        for (int j = 0; j < EOUT; j++) e[j] = Wi[EOUT * 128 + j];
        #pragma unroll 4
        for (int c = 0; c < 128; c++) {
            float x = Xs[c * XPAD + p];
            #pragma unroll
            for (int j = 0; j < EOUT; j++) e[j] = fmaf(Wi[j * 128 + c], x, e[j]);
        }
        float r = 0.f;
        #pragma unroll
        for (int j = 0; j < EOUT; j++) r = fmaf(e[j], e[j], r);
        const int n = n0 + p;
        float* eo = e_out + (size_t)b * EOUT * NN + n;
        #pragma unroll
        for (int j = 0; j < EOUT; j++) eo[(size_t)j * NN] = e[j];
        g_tA[b * NN + n] = make_float4(e[0], e[1], e[2], e[3]);
        g_tB[b * NN + n] = make_float2(e[4], r);
    }
}

// ================================================================
// min-heap sift (root = smallest kept score; we keep 30 LARGEST s').
// hd/hi pre-offset by thread column; slot stride = 128.
// ================================================================
__device__ __forceinline__ void sift_min(float* hd, int* hi, int pos, float s, int id)
{
    while (true) {
        int l = 2 * pos + 1, r = l + 1;
        float lv = (l < KSEL) ? hd[l * 128] : FINF;
        float rv = (r < KSEL) ? hd[r * 128] : FINF;
        int   ch; float cv;
        if (lv <= rv) { ch = l; cv = lv; } else { ch = r; cv = rv; }
        if (cv >= s) break;
        hd[pos * 128] = cv; hi[pos * 128] = hi[ch * 128];
        pos = ch;
    }
    hd[pos * 128] = s; hi[pos * 128] = id;
}

// ================================================================
// Phase 2a: partial top-30 (largest s' = dot - r/2) over one 1024-slice.
// 1 query per thread; f32x2 scoring; window-4 batched uniform loads.
// ================================================================
__global__ void __launch_bounds__(KQT) knn_partial_kernel()
{
    __shared__ float hd[KSEL * KQT];   // 15KB
    __shared__ int   hi[KSEL * KQT];   // 15KB
    __shared__ float qs[QCAP * KQT];   // 4KB
    __shared__ int   qi[QCAP * KQT];   // 4KB

    const int tid  = threadIdx.x;
    const int b    = blockIdx.x >> 7;             // 128 blocks/batch (32 qblk x 4 sl)
    const int qblk = (blockIdx.x >> 2) & 31;
    const int sl   = blockIdx.x & 3;
    const int q    = (qblk << 7) + tid;
    const int base = sl * SLEN;

    const ulonglong2* tA = (const ulonglong2*)(g_tA + b * NN);
    const unsigned long long* tB = (const unsigned long long*)(g_tB + b * NN);

    float4 qa = g_tA[b * NN + q];
    float2 qb = g_tB[b * NN + q];
    unsigned long long P01, P23, PK;
    asm("mov.b64 %0,{%1,%2};" : "=l"(P01) : "r"(__float_as_uint(qa.x)), "r"(__float_as_uint(qa.y)));
    asm("mov.b64 %0,{%1,%2};" : "=l"(P23) : "r"(__float_as_uint(qa.z)), "r"(__float_as_uint(qa.w)));
    asm("mov.b64 %0,{%1,%2};" : "=l"(PK)  : "r"(__float_as_uint(qb.x)), "r"(__float_as_uint(-0.5f)));

    float* hd0 = hd + tid; int* hi0 = hi + tid;
    float* qs0 = qs + tid; int* qi0 = qi + tid;

    #pragma unroll
    for (int j = 0; j < KSEL; j++) { hd0[j * 128] = FNINF; hi0[j * 128] = 0; }

    float tau = FNINF;
    int   cnt = 0;

    #pragma unroll 1
    for (int m = base; m < base + SLEN; m += 4) {
        ulonglong2 A[4]; unsigned long long Bv[4];
        #pragma unroll
        for (int j = 0; j < 4; j++) { A[j] = tA[m + j]; Bv[j] = tB[m + j]; }

        #pragma unroll
        for (int j = 0; j < 4; j++) {
            unsigned long long a;
            asm("mul.rn.f32x2 %0,%1,%2;"    : "=l"(a) : "l"(A[j].x), "l"(P01));
            asm("fma.rn.f32x2 %0,%1,%2,%3;" : "=l"(a) : "l"(A[j].y), "l"(P23), "l"(a));
            asm("fma.rn.f32x2 %0,%1,%2,%3;" : "=l"(a) : "l"(Bv[j]),  "l"(PK),  "l"(a));
            float s = __uint_as_float((unsigned)a) + __uint_as_float((unsigned)(a >> 32));
            if (s > tau) { qs0[cnt * 128] = s; qi0[cnt * 128] = m + j; cnt++; }
        }

        if (__any_sync(0xffffffffu, cnt > 4)) {
            for (int j = 0; j < cnt; j++) {
                float v = qs0[j * 128];
                if (v > hd0[0]) sift_min(hd0, hi0, 0, v, qi0[j * 128]);
            }
            cnt = 0;
            tau = hd0[0];
        }
    }
    for (int j = 0; j < cnt; j++) {
        float v = qs0[j * 128];
        if (v > hd0[0]) sift_min(hd0, hi0, 0, v, qi0[j * 128]);
    }

    // transposed partial emit: [sl*KSEL + j][bq]  (coalesced)
    const size_t bq = (size_t)b * NN + q;
    #pragma unroll
    for (int j = 0; j < KSEL; j++) {
        g_pd[(size_t)(sl * KSEL + j) * BNN + bq] = hd0[j * 128];
        g_pi[(size_t)(sl * KSEL + j) * BNN + bq] = hi0[j * 128];
    }
}

// ================================================================
// Phase 2b: merge 4x30 partials -> global top-30. Thread per query,
// smem heap; prefill with slice 0 (a valid kept-set), insert rest.
// ================================================================
__global__ void __launch_bounds__(128) knn_merge_kernel()
{
    __shared__ float hd[KSEL * 128];
    __shared__ int   hi[KSEL * 128];

    const int tid = threadIdx.x;
    const size_t bq = (size_t)blockIdx.x * 128 + tid;

    float* hd0 = hd + tid; int* hi0 = hi + tid;

    #pragma unroll
    for (int j = 0; j < KSEL; j++) {
        hd0[j * 128] = g_pd[(size_t)j * BNN + bq];
        hi0[j * 128] = g_pi[(size_t)j * BNN + bq];
    }
    #pragma unroll
    for (int i = KSEL / 2 - 1; i >= 0; i--)
        sift_min(hd0, hi0, i, hd0[i * 128], hi0[i * 128]);

    #pragma unroll 1
    for (int sj = KSEL; sj < NSLICE * KSEL; sj++) {
        float s = g_pd[(size_t)sj * BNN + bq];
        int  id = g_pi[(size_t)sj * BNN + bq];
        if (s > hd0[0]) sift_min(hd0, hi0, 0, s, id);
    }

    int* dst = g_nn + bq * KSEL;
    #pragma unroll
    for (int j = 0; j < KSEL; j++) dst[j] = hi0[j * 128];
}

// ================================================================
// Phase 3: warp-per-query gather-max over 30 neighbors + 13x128 conv
// ================================================================
__global__ void __launch_bounds__(256) gather_kernel(
    const float* __restrict__ W_sem, const float* __restrict__ b_sem,
    float* __restrict__ p_out)
{
    const int warp = (blockIdx.x << 3) + (threadIdx.x >> 5);
    const int lane = threadIdx.x & 31;
    const int b = warp >> 12, n = warp & (NN - 1);

    const int* nnp = g_nn + (size_t)warp * KSEL;
    int myid = nnp[lane < KSEL ? lane : 0];

    const float* base = g_fsemT + ((size_t)b * NN) * CIN + (lane << 2);
    float4 vmax = make_float4(FNINF, FNINF, FNINF, FNINF);
    #pragma unroll 6
    for (int k = 0; k < KSEL; k++) {
        int j = __shfl_sync(0xffffffffu, myid, k);
        float4 v = *(const float4*)(base + (size_t)j * CIN);
        vmax.x = fmaxf(vmax.x, v.x);
        vmax.y = fmaxf(vmax.y, v.y);
        vmax.z = fmaxf(vmax.z, v.z);
        vmax.w = fmaxf(vmax.w, v.w);
    }

    float out[SEMOUT];
    #pragma unroll
    for (int o = 0; o < SEMOUT; o++) {
        float4 w = *(const float4*)(W_sem + o * CIN + (lane << 2));
        float a = w.x * vmax.x;
        a = fmaf(w.y, vmax.y, a);
        a = fmaf(w.z, vmax.z, a);
        a = fmaf(w.w, vmax.w, a);
        a += __shfl_xor_sync(0xffffffffu, a, 16);
        a += __shfl_xor_sync(0xffffffffu, a, 8);
        a += __shfl_xor_sync(0xffffffffu, a, 4);
        a += __shfl_xor_sync(0xffffffffu, a, 2);
        a += __shfl_xor_sync(0xffffffffu, a, 1);
        out[o] = a;
    }
    if (lane == 0) {
        float* dst = p_out + ((size_t)b * SEMOUT) * NN + n;
        #pragma unroll
        for (int o = 0; o < SEMOUT; o++)
            dst[(size_t)o * NN] = out[o] + b_sem[o];
    }
}

// ================================================================
extern "C" void kernel_launch(void* const* d_in, const int* in_sizes, int n_in,
                              void* d_out, int out_size)
{
    (void)in_sizes; (void)n_in; (void)out_size;
    const float* f_sem   = (const float*)d_in[0];
    const float* f_ins   = (const float*)d_in[1];
    const float* W_adapt = (const float*)d_in[2];
    const float* b_adapt = (const float*)d_in[3];
    const float* gamma   = (const float*)d_in[4];
    const float* beta    = (const float*)d_in[5];
    const float* W_ins   = (const float*)d_in[6];
    const float* b_ins   = (const float*)d_in[7];
    const float* W_sem   = (const float*)d_in[8];
    const float* b_sem   = (const float*)d_in[9];

    float* p_out = (float*)d_out;                       // [B,13,N]
    float* e_out = p_out + (size_t)BB * SEMOUT * NN;    // [B,5,N]

    const int smem1 = (32 * WPAD + 128 * XPAD + EOUT * 128 + 8) * 4;
    cudaFuncSetAttribute(phase1_kernel, cudaFuncAttributeMaxDynamicSharedMemorySize, smem1);

    phase1_kernel<<<BB * (NN / TP), 128, smem1>>>(
        f_sem, f_ins, W_adapt, b_adapt, gamma, beta, W_ins, b_ins, e_out);
    knn_partial_kernel<<<BB * (NN / KQT) * NSLICE, KQT>>>();
    knn_merge_kernel<<<BNN / 128, 128>>>();
    gather_kernel<<<BNN / 8, 256>>>(W_sem, b_sem, p_out);
}

// round 8
// speedup vs baseline: 1.3847x; 1.3847x over previous
#include <cuda_runtime.h>
#include <math_constants.h>

#define BB     8
#define NN     4096
#define BNN    (BB * NN)
#define CIN    128
#define EOUT   5
#define SEMOUT 13
#define KSEL   30
#define QCAP   16
#define TP     32
#define XPAD   36
#define WPAD   129
#define NSLICE 2
#define SLEN   (NN / NSLICE)
#define KQT    128

#define FINF  __int_as_float(0x7f800000)
#define FNINF __int_as_float(0xff800000)

// ---------------- scratch (static __device__, no runtime alloc) ----------------
__device__ float  g_fsemT[BNN * CIN];            // 16MB [b][n][c]
__device__ float4 g_tA[BNN];                     // (e0,e1,e2,e3)
__device__ float2 g_tB[BNN];                     // (e4, r=||e||^2)
__device__ int    g_nn[BNN * KSEL];              // final neighbor indices
__device__ float  g_pd[BNN * NSLICE * KSEL];     // partial scores (s' = dot - r/2)
__device__ int    g_pi[BNN * NSLICE * KSEL];     // partial indices

// ================================================================
// Phase 1 (R4 structure; GEMM accumulation in packed f32x2)
// ================================================================
__global__ void __launch_bounds__(128, 4) phase1_kernel(
    const float* __restrict__ f_sem, const float* __restrict__ f_ins,
    const float* __restrict__ W_adapt, const float* __restrict__ b_adapt,
    const float* __restrict__ gamma, const float* __restrict__ beta,
    const float* __restrict__ W_ins, const float* __restrict__ b_ins,
    float* __restrict__ e_out)
{
    extern __shared__ float sm1[];
    float* Ws = sm1;                      // 32*129
    float* Xs = sm1 + 32 * WPAD;          // 128*36 (reused as Ys)
    float* Wi = Xs + 128 * XPAD;          // 5*128 + 8

    const int tid = threadIdx.x;
    const int blk = blockIdx.x;
    const int b   = blk >> 7;
    const int n0  = (blk & 127) * TP;

    for (int i = tid; i < EOUT * 128; i += 128) Wi[i] = W_ins[i];
    if (tid < EOUT) Wi[EOUT * 128 + tid] = b_ins[tid];

    const float* fs = f_sem + ((size_t)b * CIN) * NN + n0;
    for (int i = tid; i < 128 * TP; i += 128) {
        int c = i >> 5, p = i & 31;
        Xs[c * XPAD + p] = fs[(size_t)c * NN + p];
    }
    __syncthreads();

    {
        float* dst = g_fsemT + ((size_t)(b * NN + n0)) * CIN + tid;
        #pragma unroll 4
        for (int p = 0; p < TP; p++)
            dst[(size_t)p * CIN] = Xs[tid * XPAD + p];
    }

    // GEMM: thread = output channel tid; 32 points as 16 packed f32x2 accs.
    // acc2[i] holds points (2i, 2i+1).
    unsigned long long acc2[16];
    #pragma unroll
    for (int i = 0; i < 16; i++) acc2[i] = 0ull;

    #pragma unroll 1
    for (int ch = 0; ch < 4; ch++) {
        if (ch) __syncthreads();
        for (int i = tid; i < 32 * 128; i += 128) {
            int o  = i >> 5;
            int cc = i & 31;
            Ws[cc * WPAD + o] = W_adapt[o * 128 + ch * 32 + cc];
        }
        __syncthreads();

        #pragma unroll 4
        for (int cc = 0; cc < 32; cc++) {
            float w = Ws[cc * WPAD + tid];
            unsigned long long w2;
            asm("mov.b64 %0,{%1,%1};" : "=l"(w2) : "r"(__float_as_uint(w)));
            const ulonglong2* xr = (const ulonglong2*)(Xs + (ch * 32 + cc) * XPAD);
            #pragma unroll
            for (int q8 = 0; q8 < 8; q8++) {
                ulonglong2 x = xr[q8];
                asm("fma.rn.f32x2 %0,%1,%2,%3;" : "=l"(acc2[2*q8])   : "l"(w2), "l"(x.x), "l"(acc2[2*q8]));
                asm("fma.rn.f32x2 %0,%1,%2,%3;" : "=l"(acc2[2*q8+1]) : "l"(w2), "l"(x.y), "l"(acc2[2*q8+1]));
            }
        }
    }

    // epilogue: identical scalar ops to R4 (unpack first)
    const float g  = gamma[tid];
    const float bb = fmaf(g, b_adapt[tid], beta[tid]);
    const float* fi = f_ins + ((size_t)(b * CIN + tid)) * NN + n0;
    float y[TP];
    #pragma unroll
    for (int i = 0; i < 16; i++) {
        float a0 = __uint_as_float((unsigned)acc2[i]);
        float a1 = __uint_as_float((unsigned)(acc2[i] >> 32));
        y[2*i]   = fi[2*i]   + fmaxf(fmaf(g, a0, bb), 0.f);
        y[2*i+1] = fi[2*i+1] + fmaxf(fmaf(g, a1, bb), 0.f);
    }
    __syncthreads();
    #pragma unroll
    for (int p = 0; p < TP; p++) Xs[tid * XPAD + p] = y[p];
    __syncthreads();

    if (tid < TP) {
        const int p = tid;
        float e[EOUT];
        #pragma unroll
        for (int j = 0; j < EOUT; j++) e[j] = Wi[EOUT * 128 + j];
        #pragma unroll 4
        for (int c = 0; c < 128; c++) {
            float x = Xs[c * XPAD + p];
            #pragma unroll
            for (int j = 0; j < EOUT; j++) e[j] = fmaf(Wi[j * 128 + c], x, e[j]);
        }
        float r = 0.f;
        #pragma unroll
        for (int j = 0; j < EOUT; j++) r = fmaf(e[j], e[j], r);
        const int n = n0 + p;
        float* eo = e_out + (size_t)b * EOUT * NN + n;
        #pragma unroll
        for (int j = 0; j < EOUT; j++) eo[(size_t)j * NN] = e[j];
        g_tA[b * NN + n] = make_float4(e[0], e[1], e[2], e[3]);
        g_tB[b * NN + n] = make_float2(e[4], r);
    }
}

// ================================================================
// min-heap sift (root = smallest kept; we keep 30 LARGEST s').
// hd/hi pre-offset by thread column; slot stride = KQT.
// ================================================================
__device__ __forceinline__ void sift_min(float* hd, int* hi, int pos, float s, int id)
{
    while (true) {
        int l = 2 * pos + 1, r = l + 1;
        float lv = (l < KSEL) ? hd[l * KQT] : FINF;
        float rv = (r < KSEL) ? hd[r * KQT] : FINF;
        int   ch; float cv;
        if (lv <= rv) { ch = l; cv = lv; } else { ch = r; cv = rv; }
        if (cv >= s) break;
        hd[pos * KQT] = cv; hi[pos * KQT] = hi[ch * KQT];
        pos = ch;
    }
    hd[pos * KQT] = s; hi[pos * KQT] = id;
}

__device__ __forceinline__ float f2_score(
    const ulonglong2* __restrict__ tA, const unsigned long long* __restrict__ tB,
    int m, unsigned long long P01, unsigned long long P23, unsigned long long PK)
{
    ulonglong2 t = __ldg(&tA[m]);
    unsigned long long u = __ldg(&tB[m]);
    unsigned long long a;
    asm("mul.rn.f32x2 %0,%1,%2;"    : "=l"(a) : "l"(t.x), "l"(P01));
    asm("fma.rn.f32x2 %0,%1,%2,%3;" : "=l"(a) : "l"(t.y), "l"(P23), "l"(a));
    asm("fma.rn.f32x2 %0,%1,%2,%3;" : "=l"(a) : "l"(u),   "l"(PK),  "l"(a));
    return __uint_as_float((unsigned)a) + __uint_as_float((unsigned)(a >> 32));
}

// ================================================================
// Phase 2a: R4 skeleton — partial top-30 (largest s') over one 2048-slice.
// ================================================================
__global__ void __launch_bounds__(KQT, 4) knn_partial_kernel()
{
    __shared__ float hd[KSEL * KQT];
    __shared__ int   hi[KSEL * KQT];
    __shared__ float qs[QCAP * KQT];
    __shared__ int   qi[QCAP * KQT];

    const int tid  = threadIdx.x;
    const int b    = blockIdx.x >> 6;             // 64 blocks per batch
    const int qblk = (blockIdx.x >> 1) & 31;
    const int sl   = blockIdx.x & 1;
    const int q    = (qblk << 7) + tid;
    const int base = sl * SLEN;

    const ulonglong2* tA = (const ulonglong2*)(g_tA + b * NN);
    const unsigned long long* tB = (const unsigned long long*)(g_tB + b * NN);

    float4 qa = g_tA[b * NN + q];
    float2 qb = g_tB[b * NN + q];
    unsigned long long P01, P23, PK;
    asm("mov.b64 %0,{%1,%2};" : "=l"(P01) : "r"(__float_as_uint(qa.x)), "r"(__float_as_uint(qa.y)));
    asm("mov.b64 %0,{%1,%2};" : "=l"(P23) : "r"(__float_as_uint(qa.z)), "r"(__float_as_uint(qa.w)));
    asm("mov.b64 %0,{%1,%2};" : "=l"(PK)  : "r"(__float_as_uint(qb.x)), "r"(__float_as_uint(-0.5f)));

    float* myhd = hd + tid; int* myhi = hi + tid;
    float* myqs = qs + tid; int* myqi = qi + tid;

    // prefill with first 30 candidates of slice, heapify (min-heap of kept)
    #pragma unroll
    for (int j = 0; j < KSEL; j++) {
        myhd[j * KQT] = f2_score(tA, tB, base + j, P01, P23, PK);
        myhi[j * KQT] = base + j;
    }
    #pragma unroll
    for (int i = KSEL / 2 - 1; i >= 0; i--)
        sift_min(myhd, myhi, i, myhd[i * KQT], myhi[i * KQT]);

    float tau = myhd[0];
    int   cnt = 0;
    int   m   = base + KSEL;
    const int mend8 = base + KSEL + ((SLEN - KSEL) & ~7);

    #pragma unroll 1
    for (; m < mend8; m += 8) {
        #pragma unroll
        for (int uu = 0; uu < 8; uu++) {
            float s = f2_score(tA, tB, m + uu, P01, P23, PK);
            if (s > tau) { myqs[cnt * KQT] = s; myqi[cnt * KQT] = m + uu; cnt++; }
        }
        if (__any_sync(0xffffffffu, cnt > 8)) {
            for (int j = 0; j < cnt; j++) {
                float v = myqs[j * KQT];
                if (v > myhd[0]) sift_min(myhd, myhi, 0, v, myqi[j * KQT]);
            }
            cnt = 0;
            tau = myhd[0];
        }
    }
    for (; m < base + SLEN; m++) {
        float s = f2_score(tA, tB, m, P01, P23, PK);
        if (s > tau) { myqs[cnt * KQT] = s; myqi[cnt * KQT] = m; cnt++; }
    }
    for (int j = 0; j < cnt; j++) {
        float v = myqs[j * KQT];
        if (v > myhd[0]) sift_min(myhd, myhi, 0, v, myqi[j * KQT]);
    }

    const size_t off = ((size_t)(b * NN + q) * NSLICE + sl) * KSEL;
    #pragma unroll
    for (int j = 0; j < KSEL; j++) {
        g_pd[off + j] = myhd[j * KQT];
        g_pi[off + j] = myhi[j * KQT];
    }
}

// ================================================================
// Phase 2b: merge 2x30 partials -> 30 LARGEST s' (tie: smaller index).
// (verbatim R5 merge — proven)
// ================================================================
__global__ void __launch_bounds__(256) knn_merge_kernel()
{
    const int wq   = (blockIdx.x << 3) + (threadIdx.x >> 5);
    const int lane = threadIdx.x & 31;

    const size_t off = (size_t)wq * (NSLICE * KSEL);
    float s0 = FNINF, s1 = FNINF;
    int   i0 = 0x7fffffff, i1 = 0x7fffffff;
    if (lane < KSEL) {
        s0 = g_pd[off + lane];         i0 = g_pi[off + lane];
        s1 = g_pd[off + KSEL + lane];  i1 = g_pi[off + KSEL + lane];
    }

    int r0 = 0, r1 = 0;
    #pragma unroll
    for (int j = 0; j < KSEL; j++) {
        float a  = __shfl_sync(0xffffffffu, s0, j);
        int   ai = __shfl_sync(0xffffffffu, i0, j);
        r0 += (a > s0) || (a == s0 && ai < i0);
        r1 += (a > s1) || (a == s1 && ai < i1);
        float c  = __shfl_sync(0xffffffffu, s1, j);
        int   ci = __shfl_sync(0xffffffffu, i1, j);
        r0 += (c > s0) || (c == s0 && ci < i0);
        r1 += (c > s1) || (c == s1 && ci < i1);
    }
    int* dst = g_nn + (size_t)wq * KSEL;
    if (lane < KSEL) {
        if (r0 < KSEL) dst[r0] = i0;
        if (r1 < KSEL) dst[r1] = i1;
    }
}

// ================================================================
// Phase 3: warp-per-query gather-max over 30 neighbors + 13x128 conv
// ================================================================
__global__ void __launch_bounds__(256) gather_kernel(
    const float* __restrict__ W_sem, const float* __restrict__ b_sem,
    float* __restrict__ p_out)
{
    const int warp = (blockIdx.x << 3) + (threadIdx.x >> 5);
    const int lane = threadIdx.x & 31;
    const int b = warp >> 12, n = warp & (NN - 1);

    const int* nnp = g_nn + (size_t)warp * KSEL;
    int myid = nnp[lane < KSEL ? lane : 0];

    const float* base = g_fsemT + ((size_t)b * NN) * CIN + (lane << 2);
    float4 vmax = make_float4(FNINF, FNINF, FNINF, FNINF);
    #pragma unroll 6
    for (int k = 0; k < KSEL; k++) {
        int j = __shfl_sync(0xffffffffu, myid, k);
        float4 v = *(const float4*)(base + (size_t)j * CIN);
        vmax.x = fmaxf(vmax.x, v.x);
        vmax.y = fmaxf(vmax.y, v.y);
        vmax.z = fmaxf(vmax.z, v.z);
        vmax.w = fmaxf(vmax.w, v.w);
    }

    float out[SEMOUT];
    #pragma unroll
    for (int o = 0; o < SEMOUT; o++) {
        float4 w = *(const float4*)(W_sem + o * CIN + (lane << 2));
        float a = w.x * vmax.x;
        a = fmaf(w.y, vmax.y, a);
        a = fmaf(w.z, vmax.z, a);
        a = fmaf(w.w, vmax.w, a);
        a += __shfl_xor_sync(0xffffffffu, a, 16);
        a += __shfl_xor_sync(0xffffffffu, a, 8);
        a += __shfl_xor_sync(0xffffffffu, a, 4);
        a += __shfl_xor_sync(0xffffffffu, a, 2);
        a += __shfl_xor_sync(0xffffffffu, a, 1);
        out[o] = a;
    }
    if (lane == 0) {
        float* dst = p_out + ((size_t)b * SEMOUT) * NN + n;
        #pragma unroll
        for (int o = 0; o < SEMOUT; o++)
            dst[(size_t)o * NN] = out[o] + b_sem[o];
    }
}

// ================================================================
extern "C" void kernel_launch(void* const* d_in, const int* in_sizes, int n_in,
                              void* d_out, int out_size)
{
    (void)in_sizes; (void)n_in; (void)out_size;
    const float* f_sem   = (const float*)d_in[0];
    const float* f_ins   = (const float*)d_in[1];
    const float* W_adapt = (const float*)d_in[2];
    const float* b_adapt = (const float*)d_in[3];
    const float* gamma   = (const float*)d_in[4];
    const float* beta    = (const float*)d_in[5];
    const float* W_ins   = (const float*)d_in[6];
    const float* b_ins   = (const float*)d_in[7];
    const float* W_sem   = (const float*)d_in[8];
    const float* b_sem   = (const float*)d_in[9];

    float* p_out = (float*)d_out;                       // [B,13,N]
    float* e_out = p_out + (size_t)BB * SEMOUT * NN;    // [B,5,N]

    const int smem1 = (32 * WPAD + 128 * XPAD + EOUT * 128 + 8) * 4;
    cudaFuncSetAttribute(phase1_kernel, cudaFuncAttributeMaxDynamicSharedMemorySize, smem1);

    phase1_kernel<<<BB * (NN / TP), 128, smem1>>>(
        f_sem, f_ins, W_adapt, b_adapt, gamma, beta, W_ins, b_ins, e_out);
    knn_partial_kernel<<<BB * (NN / KQT) * NSLICE, KQT>>>();
    knn_merge_kernel<<<BNN / 8, 256>>>();
    gather_kernel<<<BNN / 8, 256>>>(W_sem, b_sem, p_out);
}

// round 9
// speedup vs baseline: 1.3904x; 1.0041x over previous
#include <cuda_runtime.h>
#include <math_constants.h>

#define BB     8
#define NN     4096
#define BNN    (BB * NN)
#define CIN    128
#define EOUT   5
#define SEMOUT 13
#define KSEL   30
#define QCAP   16
#define TP     32
#define XPAD   36
#define WPAD   129
#define NSLICE 2
#define SLEN   (NN / NSLICE)
#define KQT    128

#define FINF  __int_as_float(0x7f800000)
#define FNINF __int_as_float(0xff800000)

// ---------------- scratch (static __device__, no runtime alloc) ----------------
__device__ float  g_fsemT[BNN * CIN];            // 16MB [b][n][c]
__device__ float4 g_tA[BNN];                     // (e0,e1,e2,e3)
__device__ float2 g_tB[BNN];                     // (e4, r=||e||^2)
__device__ int    g_nn[BNN * KSEL];              // final neighbor indices
__device__ float  g_pd[BNN * NSLICE * KSEL];     // partial dists
__device__ int    g_pi[BNN * NSLICE * KSEL];     // partial indices

// ================================================================
// Phase 1 — R4 verbatim (scalar fmaf GEMM, chunked W staging)
// ================================================================
__global__ void __launch_bounds__(128, 4) phase1_kernel(
    const float* __restrict__ f_sem, const float* __restrict__ f_ins,
    const float* __restrict__ W_adapt, const float* __restrict__ b_adapt,
    const float* __restrict__ gamma, const float* __restrict__ beta,
    const float* __restrict__ W_ins, const float* __restrict__ b_ins,
    float* __restrict__ e_out)
{
    extern __shared__ float sm1[];
    float* Ws = sm1;                      // 32*129
    float* Xs = sm1 + 32 * WPAD;          // 128*36 (reused as Ys)
    float* Wi = Xs + 128 * XPAD;          // 5*128 + 8

    const int tid = threadIdx.x;
    const int blk = blockIdx.x;
    const int b   = blk >> 7;
    const int n0  = (blk & 127) * TP;

    for (int i = tid; i < EOUT * 128; i += 128) Wi[i] = W_ins[i];
    if (tid < EOUT) Wi[EOUT * 128 + tid] = b_ins[tid];

    const float* fs = f_sem + ((size_t)b * CIN) * NN + n0;
    for (int i = tid; i < 128 * TP; i += 128) {
        int c = i >> 5, p = i & 31;
        Xs[c * XPAD + p] = fs[(size_t)c * NN + p];
    }
    __syncthreads();

    {
        float* dst = g_fsemT + ((size_t)(b * NN + n0)) * CIN + tid;
        #pragma unroll 4
        for (int p = 0; p < TP; p++)
            dst[(size_t)p * CIN] = Xs[tid * XPAD + p];
    }

    float acc[TP];
    #pragma unroll
    for (int p = 0; p < TP; p++) acc[p] = 0.f;

    #pragma unroll 1
    for (int ch = 0; ch < 4; ch++) {
        if (ch) __syncthreads();
        for (int i = tid; i < 32 * 128; i += 128) {
            int o  = i >> 5;
            int cc = i & 31;
            Ws[cc * WPAD + o] = W_adapt[o * 128 + ch * 32 + cc];
        }
        __syncthreads();

        #pragma unroll 4
        for (int cc = 0; cc < 32; cc++) {
            float w = Ws[cc * WPAD + tid];
            const float4* xr = (const float4*)(Xs + (ch * 32 + cc) * XPAD);
            #pragma unroll
            for (int p4 = 0; p4 < TP / 4; p4++) {
                float4 x = xr[p4];
                acc[4 * p4 + 0] = fmaf(w, x.x, acc[4 * p4 + 0]);
                acc[4 * p4 + 1] = fmaf(w, x.y, acc[4 * p4 + 1]);
                acc[4 * p4 + 2] = fmaf(w, x.z, acc[4 * p4 + 2]);
                acc[4 * p4 + 3] = fmaf(w, x.w, acc[4 * p4 + 3]);
            }
        }
    }

    const float g  = gamma[tid];
    const float bb = fmaf(g, b_adapt[tid], beta[tid]);
    const float* fi = f_ins + ((size_t)(b * CIN + tid)) * NN + n0;
    float y[TP];
    #pragma unroll
    for (int p = 0; p < TP; p++) {
        float a = fmaxf(fmaf(g, acc[p], bb), 0.f);
        y[p] = fi[p] + a;
    }
    __syncthreads();
    #pragma unroll
    for (int p = 0; p < TP; p++) Xs[tid * XPAD + p] = y[p];
    __syncthreads();

    if (tid < TP) {
        const int p = tid;
        float e[EOUT];
        #pragma unroll
        for (int j = 0; j < EOUT; j++) e[j] = Wi[EOUT * 128 + j];
        #pragma unroll 4
        for (int c = 0; c < 128; c++) {
            float x = Xs[c * XPAD + p];
            #pragma unroll
            for (int j = 0; j < EOUT; j++) e[j] = fmaf(Wi[j * 128 + c], x, e[j]);
        }
        float r = 0.f;
        #pragma unroll
        for (int j = 0; j < EOUT; j++) r = fmaf(e[j], e[j], r);
        const int n = n0 + p;
        float* eo = e_out + (size_t)b * EOUT * NN + n;
        #pragma unroll
        for (int j = 0; j < EOUT; j++) eo[(size_t)j * NN] = e[j];
        g_tA[b * NN + n] = make_float4(e[0], e[1], e[2], e[3]);
        g_tB[b * NN + n] = make_float2(e[4], r);
    }
}

// ================================================================
// Phase 2a: R4 semantics (dist = r - 2*dot, keep 30 smallest, max-heap)
// with register double-buffered candidate prefetch (the one change).
// ================================================================
__device__ __forceinline__ void sift_max(float* hd, int* hi, int pos, float s, int id)
{
    while (true) {
        int l = 2 * pos + 1, r = l + 1;
        float lv = (l < KSEL) ? hd[l * KQT] : FNINF;
        float rv = (r < KSEL) ? hd[r * KQT] : FNINF;
        int   ch; float cv;
        if (lv >= rv) { ch = l; cv = lv; } else { ch = r; cv = rv; }
        if (cv <= s) break;
        hd[pos * KQT] = cv; hi[pos * KQT] = hi[ch * KQT];
        pos = ch;
    }
    hd[pos * KQT] = s; hi[pos * KQT] = id;
}

#define LOADW(Ab, Bb, mm) do {                                            \
    _Pragma("unroll")                                                     \
    for (int _j = 0; _j < 8; _j++) {                                      \
        Ab[_j] = __ldg(&tA4[(mm) + _j]);                                  \
        Bb[_j] = __ldg(&tB2[(mm) + _j]);                                  \
    }                                                                     \
} while (0)

#define PROCW(Ab, Bb, mm) do {                                            \
    _Pragma("unroll")                                                     \
    for (int _j = 0; _j < 8; _j++) {                                      \
        float _d = Ab[_j].x * Qa.x;                                       \
        _d = fmaf(Ab[_j].y, Qa.y, _d);                                    \
        _d = fmaf(Ab[_j].z, Qa.z, _d);                                    \
        _d = fmaf(Ab[_j].w, Qa.w, _d);                                    \
        _d = fmaf(Bb[_j].x, q4, _d);                                      \
        float _s = fmaf(-2.f, _d, Bb[_j].y);                              \
        if (_s < tau) { myqs[cnt * KQT] = _s; myqi[cnt * KQT] = (mm) + _j; cnt++; } \
    }                                                                     \
} while (0)

#define FLUSHW() do {                                                     \
    if (__any_sync(0xffffffffu, cnt > 8)) {                               \
        for (int _j = 0; _j < cnt; _j++) {                                \
            float _v = myqs[_j * KQT];                                    \
            if (_v < myhd[0]) sift_max(myhd, myhi, 0, _v, myqi[_j * KQT]);\
        }                                                                 \
        cnt = 0;                                                          \
        tau = myhd[0];                                                    \
    }                                                                     \
} while (0)

__global__ void __launch_bounds__(KQT) knn_partial_kernel()
{
    __shared__ float hd[KSEL * KQT];
    __shared__ int   hi[KSEL * KQT];
    __shared__ float qs[QCAP * KQT];
    __shared__ int   qi[QCAP * KQT];

    const int tid  = threadIdx.x;
    const int b    = blockIdx.x >> 6;             // 64 blocks per batch
    const int qblk = (blockIdx.x >> 1) & 31;
    const int sl   = blockIdx.x & 1;
    const int q    = (qblk << 7) + tid;
    const int base = sl * SLEN;

    const float4* tA4 = g_tA + b * NN;
    const float2* tB2 = g_tB + b * NN;

    const float4 Qa = __ldg(&tA4[q]);
    const float  q4 = __ldg(&tB2[q]).x;

    float* myhd = hd + tid; int* myhi = hi + tid;
    float* myqs = qs + tid; int* myqi = qi + tid;

    // prefill with first 30 candidates of slice, heapify (max-heap of kept dists)
    #pragma unroll
    for (int j = 0; j < KSEL; j++) {
        float4 ta = __ldg(&tA4[base + j]);
        float2 tb = __ldg(&tB2[base + j]);
        float d = ta.x * Qa.x;
        d = fmaf(ta.y, Qa.y, d);
        d = fmaf(ta.z, Qa.z, d);
        d = fmaf(ta.w, Qa.w, d);
        d = fmaf(tb.x, q4, d);
        myhd[j * KQT] = fmaf(-2.f, d, tb.y);
        myhi[j * KQT] = base + j;
    }
    #pragma unroll
    for (int i = KSEL / 2 - 1; i >= 0; i--)
        sift_max(myhd, myhi, i, myhd[i * KQT], myhi[i * KQT]);

    float tau = myhd[0];
    int   cnt = 0;

    const int start = base + KSEL;
    const int end   = base + SLEN;
    const int endp  = start + ((end - start) & ~15);   // pipelined region (x16)

    float4 A0[8], A1[8];
    float2 B0[8], B1[8];

    int m = start;
    if (m < endp) {
        LOADW(A0, B0, m);
        #pragma unroll 1
        for (; m < endp; m += 16) {
            LOADW(A1, B1, m + 8);                 // prefetch window i+1
            PROCW(A0, B0, m);                     // process window i
            FLUSHW();
            const int mn = (m + 16 < endp) ? (m + 16) : start;   // safe dummy
            LOADW(A0, B0, mn);                    // prefetch window i+2
            PROCW(A1, B1, m + 8);                 // process window i+1
            FLUSHW();
        }
    }
    for (; m < end; m++) {                        // scalar tail (<16)
        float4 ta = __ldg(&tA4[m]);
        float2 tb = __ldg(&tB2[m]);
        float d = ta.x * Qa.x;
        d = fmaf(ta.y, Qa.y, d);
        d = fmaf(ta.z, Qa.z, d);
        d = fmaf(ta.w, Qa.w, d);
        d = fmaf(tb.x, q4, d);
        float s = fmaf(-2.f, d, tb.y);
        if (s < tau) { myqs[cnt * KQT] = s; myqi[cnt * KQT] = m; cnt++; }
    }
    for (int j = 0; j < cnt; j++) {
        float v = myqs[j * KQT];
        if (v < myhd[0]) sift_max(myhd, myhi, 0, v, myqi[j * KQT]);
    }

    const size_t off = ((size_t)(b * NN + q) * NSLICE + sl) * KSEL;
    #pragma unroll
    for (int j = 0; j < KSEL; j++) {
        g_pd[off + j] = myhd[j * KQT];
        g_pi[off + j] = myhi[j * KQT];
    }
}

// ================================================================
// Phase 2b: merge 2x30 partials -> 30 smallest (tie: smaller index).
// (R4 verbatim)
// ================================================================
__global__ void __launch_bounds__(256) knn_merge_kernel()
{
    const int wq   = (blockIdx.x << 3) + (threadIdx.x >> 5);
    const int lane = threadIdx.x & 31;

    const size_t off = (size_t)wq * (NSLICE * KSEL);
    float s0 = FINF, s1 = FINF;
    int   i0 = 0x7fffffff, i1 = 0x7fffffff;
    if (lane < KSEL) {
        s0 = g_pd[off + lane];         i0 = g_pi[off + lane];
        s1 = g_pd[off + KSEL + lane];  i1 = g_pi[off + KSEL + lane];
    }

    int r0 = 0, r1 = 0;
    #pragma unroll
    for (int j = 0; j < KSEL; j++) {
        float a  = __shfl_sync(0xffffffffu, s0, j);
        int   ai = __shfl_sync(0xffffffffu, i0, j);
        r0 += (a < s0) || (a == s0 && ai < i0);
        r1 += (a < s1) || (a == s1 && ai < i1);
        float c  = __shfl_sync(0xffffffffu, s1, j);
        int   ci = __shfl_sync(0xffffffffu, i1, j);
        r0 += (c < s0) || (c == s0 && ci < i0);
        r1 += (c < s1) || (c == s1 && ci < i1);
    }
    int* dst = g_nn + (size_t)wq * KSEL;
    if (lane < KSEL) {
        if (r0 < KSEL) dst[r0] = i0;
        if (r1 < KSEL) dst[r1] = i1;
    }
}

// ================================================================
// Phase 3: warp-per-query gather-max over 30 neighbors + 13x128 conv
// ================================================================
__global__ void __launch_bounds__(256) gather_kernel(
    const float* __restrict__ W_sem, const float* __restrict__ b_sem,
    float* __restrict__ p_out)
{
    const int warp = (blockIdx.x << 3) + (threadIdx.x >> 5);
    const int lane = threadIdx.x & 31;
    const int b = warp >> 12, n = warp & (NN - 1);

    const int* nnp = g_nn + (size_t)warp * KSEL;
    int myid = nnp[lane < KSEL ? lane : 0];

    const float* base = g_fsemT + ((size_t)b * NN) * CIN + (lane << 2);
    float4 vmax = make_float4(FNINF, FNINF, FNINF, FNINF);
    #pragma unroll 6
    for (int k = 0; k < KSEL; k++) {
        int j = __shfl_sync(0xffffffffu, myid, k);
        float4 v = *(const float4*)(base + (size_t)j * CIN);
        vmax.x = fmaxf(vmax.x, v.x);
        vmax.y = fmaxf(vmax.y, v.y);
        vmax.z = fmaxf(vmax.z, v.z);
        vmax.w = fmaxf(vmax.w, v.w);
    }

    float out[SEMOUT];
    #pragma unroll
    for (int o = 0; o < SEMOUT; o++) {
        float4 w = *(const float4*)(W_sem + o * CIN + (lane << 2));
        float a = w.x * vmax.x;
        a = fmaf(w.y, vmax.y, a);
        a = fmaf(w.z, vmax.z, a);
        a = fmaf(w.w, vmax.w, a);
        a += __shfl_xor_sync(0xffffffffu, a, 16);
        a += __shfl_xor_sync(0xffffffffu, a, 8);
        a += __shfl_xor_sync(0xffffffffu, a, 4);
        a += __shfl_xor_sync(0xffffffffu, a, 2);
        a += __shfl_xor_sync(0xffffffffu, a, 1);
        out[o] = a;
    }
    if (lane == 0) {
        float* dst = p_out + ((size_t)b * SEMOUT) * NN + n;
        #pragma unroll
        for (int o = 0; o < SEMOUT; o++)
            dst[(size_t)o * NN] = out[o] + b_sem[o];
    }
}

// ================================================================
extern "C" void kernel_launch(void* const* d_in, const int* in_sizes, int n_in,
                              void* d_out, int out_size)
{
    (void)in_sizes; (void)n_in; (void)out_size;
    const float* f_sem   = (const float*)d_in[0];
    const float* f_ins   = (const float*)d_in[1];
    const float* W_adapt = (const float*)d_in[2];
    const float* b_adapt = (const float*)d_in[3];
    const float* gamma   = (const float*)d_in[4];
    const float* beta    = (const float*)d_in[5];
    const float* W_ins   = (const float*)d_in[6];
    const float* b_ins   = (const float*)d_in[7];
    const float* W_sem   = (const float*)d_in[8];
    const float* b_sem   = (const float*)d_in[9];

    float* p_out = (float*)d_out;                       // [B,13,N]
    float* e_out = p_out + (size_t)BB * SEMOUT * NN;    // [B,5,N]

    const int smem1 = (32 * WPAD + 128 * XPAD + EOUT * 128 + 8) * 4;
    cudaFuncSetAttribute(phase1_kernel, cudaFuncAttributeMaxDynamicSharedMemorySize, smem1);

    phase1_kernel<<<BB * (NN / TP), 128, smem1>>>(
        f_sem, f_ins, W_adapt, b_adapt, gamma, beta, W_ins, b_ins, e_out);
    knn_partial_kernel<<<BB * (NN / KQT) * NSLICE, KQT>>>();
    knn_merge_kernel<<<BNN / 8, 256>>>();
    gather_kernel<<<BNN / 8, 256>>>(W_sem, b_sem, p_out);
}

// round 10
// speedup vs baseline: 1.4515x; 1.0440x over previous
#include <cuda_runtime.h>
#include <math_constants.h>

#define BB     8
#define NN     4096
#define BNN    (BB * NN)
#define CIN    128
#define EOUT   5
#define SEMOUT 13
#define KSEL   30
#define QCAP   16
#define TP     32
#define XPAD   36
#define WPAD   129
#define NSLICE 2
#define SLEN   (NN / NSLICE)
#define KQT    128
#define CHUNK  256

#define FINF  __int_as_float(0x7f800000)
#define FNINF __int_as_float(0xff800000)

// ---------------- scratch (static __device__, no runtime alloc) ----------------
__device__ float  g_fsemT[BNN * CIN];            // 16MB [b][n][c]
__device__ float4 g_tA[BNN];                     // (e0,e1,e2,e3)
__device__ float2 g_tB[BNN];                     // (e4, r=||e||^2)
__device__ int    g_nn[BNN * KSEL];              // final neighbor indices
__device__ float  g_pd[BNN * NSLICE * KSEL];     // partial dists
__device__ int    g_pi[BNN * NSLICE * KSEL];     // partial indices

// ================================================================
// Phase 1 — R4 verbatim
// ================================================================
__global__ void __launch_bounds__(128, 4) phase1_kernel(
    const float* __restrict__ f_sem, const float* __restrict__ f_ins,
    const float* __restrict__ W_adapt, const float* __restrict__ b_adapt,
    const float* __restrict__ gamma, const float* __restrict__ beta,
    const float* __restrict__ W_ins, const float* __restrict__ b_ins,
    float* __restrict__ e_out)
{
    extern __shared__ float sm1[];
    float* Ws = sm1;                      // 32*129
    float* Xs = sm1 + 32 * WPAD;          // 128*36 (reused as Ys)
    float* Wi = Xs + 128 * XPAD;          // 5*128 + 8

    const int tid = threadIdx.x;
    const int blk = blockIdx.x;
    const int b   = blk >> 7;
    const int n0  = (blk & 127) * TP;

    for (int i = tid; i < EOUT * 128; i += 128) Wi[i] = W_ins[i];
    if (tid < EOUT) Wi[EOUT * 128 + tid] = b_ins[tid];

    const float* fs = f_sem + ((size_t)b * CIN) * NN + n0;
    for (int i = tid; i < 128 * TP; i += 128) {
        int c = i >> 5, p = i & 31;
        Xs[c * XPAD + p] = fs[(size_t)c * NN + p];
    }
    __syncthreads();

    {
        float* dst = g_fsemT + ((size_t)(b * NN + n0)) * CIN + tid;
        #pragma unroll 4
        for (int p = 0; p < TP; p++)
            dst[(size_t)p * CIN] = Xs[tid * XPAD + p];
    }

    float acc[TP];
    #pragma unroll
    for (int p = 0; p < TP; p++) acc[p] = 0.f;

    #pragma unroll 1
    for (int ch = 0; ch < 4; ch++) {
        if (ch) __syncthreads();
        for (int i = tid; i < 32 * 128; i += 128) {
            int o  = i >> 5;
            int cc = i & 31;
            Ws[cc * WPAD + o] = W_adapt[o * 128 + ch * 32 + cc];
        }
        __syncthreads();

        #pragma unroll 4
        for (int cc = 0; cc < 32; cc++) {
            float w = Ws[cc * WPAD + tid];
            const float4* xr = (const float4*)(Xs + (ch * 32 + cc) * XPAD);
            #pragma unroll
            for (int p4 = 0; p4 < TP / 4; p4++) {
                float4 x = xr[p4];
                acc[4 * p4 + 0] = fmaf(w, x.x, acc[4 * p4 + 0]);
                acc[4 * p4 + 1] = fmaf(w, x.y, acc[4 * p4 + 1]);
                acc[4 * p4 + 2] = fmaf(w, x.z, acc[4 * p4 + 2]);
                acc[4 * p4 + 3] = fmaf(w, x.w, acc[4 * p4 + 3]);
            }
        }
    }

    const float g  = gamma[tid];
    const float bb = fmaf(g, b_adapt[tid], beta[tid]);
    const float* fi = f_ins + ((size_t)(b * CIN + tid)) * NN + n0;
    float y[TP];
    #pragma unroll
    for (int p = 0; p < TP; p++) {
        float a = fmaxf(fmaf(g, acc[p], bb), 0.f);
        y[p] = fi[p] + a;
    }
    __syncthreads();
    #pragma unroll
    for (int p = 0; p < TP; p++) Xs[tid * XPAD + p] = y[p];
    __syncthreads();

    if (tid < TP) {
        const int p = tid;
        float e[EOUT];
        #pragma unroll
        for (int j = 0; j < EOUT; j++) e[j] = Wi[EOUT * 128 + j];
        #pragma unroll 4
        for (int c = 0; c < 128; c++) {
            float x = Xs[c * XPAD + p];
            #pragma unroll
            for (int j = 0; j < EOUT; j++) e[j] = fmaf(Wi[j * 128 + c], x, e[j]);
        }
        float r = 0.f;
        #pragma unroll
        for (int j = 0; j < EOUT; j++) r = fmaf(e[j], e[j], r);
        const int n = n0 + p;
        float* eo = e_out + (size_t)b * EOUT * NN + n;
        #pragma unroll
        for (int j = 0; j < EOUT; j++) eo[(size_t)j * NN] = e[j];
        g_tA[b * NN + n] = make_float4(e[0], e[1], e[2], e[3]);
        g_tB[b * NN + n] = make_float2(e[4], r);
    }
}

// ================================================================
// Phase 2a: R4 semantics; candidates staged per 256-chunk into smem,
// scan reads broadcast LDS (the one change).
// ================================================================
__device__ __forceinline__ void sift_max(float* hd, int* hi, int pos, float s, int id)
{
    while (true) {
        int l = 2 * pos + 1, r = l + 1;
        float lv = (l < KSEL) ? hd[l * KQT] : FNINF;
        float rv = (r < KSEL) ? hd[r * KQT] : FNINF;
        int   ch; float cv;
        if (lv >= rv) { ch = l; cv = lv; } else { ch = r; cv = rv; }
        if (cv <= s) break;
        hd[pos * KQT] = cv; hi[pos * KQT] = hi[ch * KQT];
        pos = ch;
    }
    hd[pos * KQT] = s; hi[pos * KQT] = id;
}

__global__ void __launch_bounds__(KQT) knn_partial_kernel()
{
    extern __shared__ float smk[];
    float4* st4 = (float4*)smk;                    // CHUNK * 16B
    float2* st2 = (float2*)(st4 + CHUNK);          // CHUNK * 8B
    float*  hd  = (float*)(st2 + CHUNK);           // KSEL*KQT
    int*    hi  = (int*)(hd + KSEL * KQT);
    float*  qs  = (float*)(hi + KSEL * KQT);       // QCAP*KQT
    int*    qi  = (int*)(qs + QCAP * KQT);

    const int tid  = threadIdx.x;
    const int b    = blockIdx.x >> 6;              // 64 blocks per batch
    const int qblk = (blockIdx.x >> 1) & 31;
    const int sl   = blockIdx.x & 1;
    const int q    = (qblk << 7) + tid;
    const int base = sl * SLEN;

    const float4* tA4 = g_tA + b * NN;
    const float2* tB2 = g_tB + b * NN;

    const float4 Qa = __ldg(&tA4[q]);
    const float  q4 = __ldg(&tB2[q]).x;

    float* myhd = hd + tid; int* myhi = hi + tid;
    float* myqs = qs + tid; int* myqi = qi + tid;

    // stage chunk 0
    st4[tid]       = __ldg(&tA4[base + tid]);
    st2[tid]       = __ldg(&tB2[base + tid]);
    st4[tid + 128] = __ldg(&tA4[base + tid + 128]);
    st2[tid + 128] = __ldg(&tB2[base + tid + 128]);
    __syncthreads();

    // prefill with first 30 candidates (from smem), heapify (max-heap of kept)
    #pragma unroll
    for (int j = 0; j < KSEL; j++) {
        float4 ta = st4[j];
        float2 tb = st2[j];
        float d = ta.x * Qa.x;
        d = fmaf(ta.y, Qa.y, d);
        d = fmaf(ta.z, Qa.z, d);
        d = fmaf(ta.w, Qa.w, d);
        d = fmaf(tb.x, q4, d);
        myhd[j * KQT] = fmaf(-2.f, d, tb.y);
        myhi[j * KQT] = base + j;
    }
    #pragma unroll
    for (int i = KSEL / 2 - 1; i >= 0; i--)
        sift_max(myhd, myhi, i, myhd[i * KQT], myhi[i * KQT]);

    float tau = myhd[0];
    int   cnt = 0;

    #pragma unroll 1
    for (int ch = 0; ch < SLEN / CHUNK; ch++) {
        if (ch) {
            __syncthreads();               // all scans of prev chunk done
            const int mg = base + ch * CHUNK;
            st4[tid]       = __ldg(&tA4[mg + tid]);
            st2[tid]       = __ldg(&tB2[mg + tid]);
            st4[tid + 128] = __ldg(&tA4[mg + tid + 128]);
            st2[tid + 128] = __ldg(&tB2[mg + tid + 128]);
            __syncthreads();
        }
        const int mgc  = base + ch * CHUNK;
        int k = (ch == 0) ? KSEL : 0;

        // align to window of 8 (only chunk 0: k=30 -> scalar 2)
        for (; k & 7; k++) {
            float4 ta = st4[k];
            float2 tb = st2[k];
            float d = ta.x * Qa.x;
            d = fmaf(ta.y, Qa.y, d);
            d = fmaf(ta.z, Qa.z, d);
            d = fmaf(ta.w, Qa.w, d);
            d = fmaf(tb.x, q4, d);
            float s = fmaf(-2.f, d, tb.y);
            if (s < tau) { myqs[cnt * KQT] = s; myqi[cnt * KQT] = mgc + k; cnt++; }
        }

        #pragma unroll 1
        for (; k < CHUNK; k += 8) {
            #pragma unroll
            for (int j = 0; j < 8; j++) {
                float4 ta = st4[k + j];
                float2 tb = st2[k + j];
                float d = ta.x * Qa.x;
                d = fmaf(ta.y, Qa.y, d);
                d = fmaf(ta.z, Qa.z, d);
                d = fmaf(ta.w, Qa.w, d);
                d = fmaf(tb.x, q4, d);
                float s = fmaf(-2.f, d, tb.y);
                if (s < tau) { myqs[cnt * KQT] = s; myqi[cnt * KQT] = mgc + k + j; cnt++; }
            }
            if (__any_sync(0xffffffffu, cnt > 8)) {
                for (int j = 0; j < cnt; j++) {
                    float v = myqs[j * KQT];
                    if (v < myhd[0]) sift_max(myhd, myhi, 0, v, myqi[j * KQT]);
                }
                cnt = 0;
                tau = myhd[0];
            }
        }
    }
    for (int j = 0; j < cnt; j++) {
        float v = myqs[j * KQT];
        if (v < myhd[0]) sift_max(myhd, myhi, 0, v, myqi[j * KQT]);
    }

    const size_t off = ((size_t)(b * NN + q) * NSLICE + sl) * KSEL;
    #pragma unroll
    for (int j = 0; j < KSEL; j++) {
        g_pd[off + j] = myhd[j * KQT];
        g_pi[off + j] = myhi[j * KQT];
    }
}

// ================================================================
// Phase 2b: merge 2x30 partials -> 30 smallest (tie: smaller index).
// (R4 verbatim)
// ================================================================
__global__ void __launch_bounds__(256) knn_merge_kernel()
{
    const int wq   = (blockIdx.x << 3) + (threadIdx.x >> 5);
    const int lane = threadIdx.x & 31;

    const size_t off = (size_t)wq * (NSLICE * KSEL);
    float s0 = FINF, s1 = FINF;
    int   i0 = 0x7fffffff, i1 = 0x7fffffff;
    if (lane < KSEL) {
        s0 = g_pd[off + lane];         i0 = g_pi[off + lane];
        s1 = g_pd[off + KSEL + lane];  i1 = g_pi[off + KSEL + lane];
    }

    int r0 = 0, r1 = 0;
    #pragma unroll
    for (int j = 0; j < KSEL; j++) {
        float a  = __shfl_sync(0xffffffffu, s0, j);
        int   ai = __shfl_sync(0xffffffffu, i0, j);
        r0 += (a < s0) || (a == s0 && ai < i0);
        r1 += (a < s1) || (a == s1 && ai < i1);
        float c  = __shfl_sync(0xffffffffu, s1, j);
        int   ci = __shfl_sync(0xffffffffu, i1, j);
        r0 += (c < s0) || (c == s0 && ci < i0);
        r1 += (c < s1) || (c == s1 && ci < i1);
    }
    int* dst = g_nn + (size_t)wq * KSEL;
    if (lane < KSEL) {
        if (r0 < KSEL) dst[r0] = i0;
        if (r1 < KSEL) dst[r1] = i1;
    }
}

// ================================================================
// Phase 3: warp-per-query gather-max over 30 neighbors + 13x128 conv
// ================================================================
__global__ void __launch_bounds__(256) gather_kernel(
    const float* __restrict__ W_sem, const float* __restrict__ b_sem,
    float* __restrict__ p_out)
{
    const int warp = (blockIdx.x << 3) + (threadIdx.x >> 5);
    const int lane = threadIdx.x & 31;
    const int b = warp >> 12, n = warp & (NN - 1);

    const int* nnp = g_nn + (size_t)warp * KSEL;
    int myid = nnp[lane < KSEL ? lane : 0];

    const float* base = g_fsemT + ((size_t)b * NN) * CIN + (lane << 2);
    float4 vmax = make_float4(FNINF, FNINF, FNINF, FNINF);
    #pragma unroll 6
    for (int k = 0; k < KSEL; k++) {
        int j = __shfl_sync(0xffffffffu, myid, k);
        float4 v = *(const float4*)(base + (size_t)j * CIN);
        vmax.x = fmaxf(vmax.x, v.x);
        vmax.y = fmaxf(vmax.y, v.y);
        vmax.z = fmaxf(vmax.z, v.z);
        vmax.w = fmaxf(vmax.w, v.w);
    }

    float out[SEMOUT];
    #pragma unroll
    for (int o = 0; o < SEMOUT; o++) {
        float4 w = *(const float4*)(W_sem + o * CIN + (lane << 2));
        float a = w.x * vmax.x;
        a = fmaf(w.y, vmax.y, a);
        a = fmaf(w.z, vmax.z, a);
        a = fmaf(w.w, vmax.w, a);
        a += __shfl_xor_sync(0xffffffffu, a, 16);
        a += __shfl_xor_sync(0xffffffffu, a, 8);
        a += __shfl_xor_sync(0xffffffffu, a, 4);
        a += __shfl_xor_sync(0xffffffffu, a, 2);
        a += __shfl_xor_sync(0xffffffffu, a, 1);
        out[o] = a;
    }
    if (lane == 0) {
        float* dst = p_out + ((size_t)b * SEMOUT) * NN + n;
        #pragma unroll
        for (int o = 0; o < SEMOUT; o++)
            dst[(size_t)o * NN] = out[o] + b_sem[o];
    }
}

// ================================================================
extern "C" void kernel_launch(void* const* d_in, const int* in_sizes, int n_in,
                              void* d_out, int out_size)
{
    (void)in_sizes; (void)n_in; (void)out_size;
    const float* f_sem   = (const float*)d_in[0];
    const float* f_ins   = (const float*)d_in[1];
    const float* W_adapt = (const float*)d_in[2];
    const float* b_adapt = (const float*)d_in[3];
    const float* gamma   = (const float*)d_in[4];
    const float* beta    = (const float*)d_in[5];
    const float* W_ins   = (const float*)d_in[6];
    const float* b_ins   = (const float*)d_in[7];
    const float* W_sem   = (const float*)d_in[8];
    const float* b_sem   = (const float*)d_in[9];

    float* p_out = (float*)d_out;                       // [B,13,N]
    float* e_out = p_out + (size_t)BB * SEMOUT * NN;    // [B,5,N]

    const int smem1 = (32 * WPAD + 128 * XPAD + EOUT * 128 + 8) * 4;
    const int smem2 = CHUNK * 24 + (KSEL * KQT + QCAP * KQT) * 8;   // 52KB

    cudaFuncSetAttribute(phase1_kernel,      cudaFuncAttributeMaxDynamicSharedMemorySize, smem1);
    cudaFuncSetAttribute(knn_partial_kernel, cudaFuncAttributeMaxDynamicSharedMemorySize, smem2);

    phase1_kernel<<<BB * (NN / TP), 128, smem1>>>(
        f_sem, f_ins, W_adapt, b_adapt, gamma, beta, W_ins, b_ins, e_out);
    knn_partial_kernel<<<BB * (NN / KQT) * NSLICE, KQT, smem2>>>();
    knn_merge_kernel<<<BNN / 8, 256>>>();
    gather_kernel<<<BNN / 8, 256>>>(W_sem, b_sem, p_out);
}

// round 11
// speedup vs baseline: 1.5145x; 1.0434x over previous
#include <cuda_runtime.h>
#include <math_constants.h>

#define BB     8
#define NN     4096
#define BNN    (BB * NN)
#define CIN    128
#define EOUT   5
#define SEMOUT 13
#define KSEL   30
#define QCAP   16
#define TP     32
#define XPAD   36
#define WPAD   129
#define NSLICE 2
#define SLEN   (NN / NSLICE)
#define KQT    128
#define CHUNK  256

#define FINF  __int_as_float(0x7f800000)
#define FNINF __int_as_float(0xff800000)

// ---------------- scratch (static __device__, no runtime alloc) ----------------
__device__ float  g_fsemT[BNN * CIN];            // 16MB [b][n][c]
__device__ float4 g_tA[BNN];                     // (e0,e1,e2,e3)
__device__ float2 g_tB[BNN];                     // (e4, r=||e||^2)
__device__ int    g_nn[BNN * KSEL];              // final neighbor indices
__device__ float  g_pd[BNN * NSLICE * KSEL];     // partial dists
__device__ int    g_pi[BNN * NSLICE * KSEL];     // partial indices

// ================================================================
// Phase 1 — R4 verbatim
// ================================================================
__global__ void __launch_bounds__(128, 4) phase1_kernel(
    const float* __restrict__ f_sem, const float* __restrict__ f_ins,
    const float* __restrict__ W_adapt, const float* __restrict__ b_adapt,
    const float* __restrict__ gamma, const float* __restrict__ beta,
    const float* __restrict__ W_ins, const float* __restrict__ b_ins,
    float* __restrict__ e_out)
{
    extern __shared__ float sm1[];
    float* Ws = sm1;                      // 32*129
    float* Xs = sm1 + 32 * WPAD;          // 128*36 (reused as Ys)
    float* Wi = Xs + 128 * XPAD;          // 5*128 + 8

    const int tid = threadIdx.x;
    const int blk = blockIdx.x;
    const int b   = blk >> 7;
    const int n0  = (blk & 127) * TP;

    for (int i = tid; i < EOUT * 128; i += 128) Wi[i] = W_ins[i];
    if (tid < EOUT) Wi[EOUT * 128 + tid] = b_ins[tid];

    const float* fs = f_sem + ((size_t)b * CIN) * NN + n0;
    for (int i = tid; i < 128 * TP; i += 128) {
        int c = i >> 5, p = i & 31;
        Xs[c * XPAD + p] = fs[(size_t)c * NN + p];
    }
    __syncthreads();

    {
        float* dst = g_fsemT + ((size_t)(b * NN + n0)) * CIN + tid;
        #pragma unroll 4
        for (int p = 0; p < TP; p++)
            dst[(size_t)p * CIN] = Xs[tid * XPAD + p];
    }

    float acc[TP];
    #pragma unroll
    for (int p = 0; p < TP; p++) acc[p] = 0.f;

    #pragma unroll 1
    for (int ch = 0; ch < 4; ch++) {
        if (ch) __syncthreads();
        for (int i = tid; i < 32 * 128; i += 128) {
            int o  = i >> 5;
            int cc = i & 31;
            Ws[cc * WPAD + o] = W_adapt[o * 128 + ch * 32 + cc];
        }
        __syncthreads();

        #pragma unroll 4
        for (int cc = 0; cc < 32; cc++) {
            float w = Ws[cc * WPAD + tid];
            const float4* xr = (const float4*)(Xs + (ch * 32 + cc) * XPAD);
            #pragma unroll
            for (int p4 = 0; p4 < TP / 4; p4++) {
                float4 x = xr[p4];
                acc[4 * p4 + 0] = fmaf(w, x.x, acc[4 * p4 + 0]);
                acc[4 * p4 + 1] = fmaf(w, x.y, acc[4 * p4 + 1]);
                acc[4 * p4 + 2] = fmaf(w, x.z, acc[4 * p4 + 2]);
                acc[4 * p4 + 3] = fmaf(w, x.w, acc[4 * p4 + 3]);
            }
        }
    }

    const float g  = gamma[tid];
    const float bb = fmaf(g, b_adapt[tid], beta[tid]);
    const float* fi = f_ins + ((size_t)(b * CIN + tid)) * NN + n0;
    float y[TP];
    #pragma unroll
    for (int p = 0; p < TP; p++) {
        float a = fmaxf(fmaf(g, acc[p], bb), 0.f);
        y[p] = fi[p] + a;
    }
    __syncthreads();
    #pragma unroll
    for (int p = 0; p < TP; p++) Xs[tid * XPAD + p] = y[p];
    __syncthreads();

    if (tid < TP) {
        const int p = tid;
        float e[EOUT];
        #pragma unroll
        for (int j = 0; j < EOUT; j++) e[j] = Wi[EOUT * 128 + j];
        #pragma unroll 4
        for (int c = 0; c < 128; c++) {
            float x = Xs[c * XPAD + p];
            #pragma unroll
            for (int j = 0; j < EOUT; j++) e[j] = fmaf(Wi[j * 128 + c], x, e[j]);
        }
        float r = 0.f;
        #pragma unroll
        for (int j = 0; j < EOUT; j++) r = fmaf(e[j], e[j], r);
        const int n = n0 + p;
        float* eo = e_out + (size_t)b * EOUT * NN + n;
        #pragma unroll
        for (int j = 0; j < EOUT; j++) eo[(size_t)j * NN] = e[j];
        g_tA[b * NN + n] = make_float4(e[0], e[1], e[2], e[3]);
        g_tB[b * NN + n] = make_float2(e[4], r);
    }
}

// ================================================================
// Phase 2a: R9 structure; heap replaced by branchless replace-max
// selection over an unordered 30-slot kept-set (the one change).
// ================================================================
__global__ void __launch_bounds__(KQT) knn_partial_kernel()
{
    extern __shared__ float smk[];
    float4* st4 = (float4*)smk;                    // CHUNK * 16B
    float2* st2 = (float2*)(st4 + CHUNK);          // CHUNK * 8B
    float*  hd  = (float*)(st2 + CHUNK);           // KSEL*KQT (unordered kept)
    int*    hi  = (int*)(hd + KSEL * KQT);
    float*  qs  = (float*)(hi + KSEL * KQT);       // QCAP*KQT
    int*    qi  = (int*)(qs + QCAP * KQT);

    const int tid  = threadIdx.x;
    const int b    = blockIdx.x >> 6;              // 64 blocks per batch
    const int qblk = (blockIdx.x >> 1) & 31;
    const int sl   = blockIdx.x & 1;
    const int q    = (qblk << 7) + tid;
    const int base = sl * SLEN;

    const float4* tA4 = g_tA + b * NN;
    const float2* tB2 = g_tB + b * NN;

    const float4 Qa = __ldg(&tA4[q]);
    const float  q4 = __ldg(&tB2[q]).x;

    float* myhd = hd + tid; int* myhi = hi + tid;
    float* myqs = qs + tid; int* myqi = qi + tid;

    // stage chunk 0
    st4[tid]       = __ldg(&tA4[base + tid]);
    st2[tid]       = __ldg(&tB2[base + tid]);
    st4[tid + 128] = __ldg(&tA4[base + tid + 128]);
    st2[tid + 128] = __ldg(&tB2[base + tid + 128]);
    __syncthreads();

    // prefill 30 slots (unordered), then one branchless rescan for tau/amax
    #pragma unroll
    for (int j = 0; j < KSEL; j++) {
        float4 ta = st4[j];
        float2 tb = st2[j];
        float d = ta.x * Qa.x;
        d = fmaf(ta.y, Qa.y, d);
        d = fmaf(ta.z, Qa.z, d);
        d = fmaf(ta.w, Qa.w, d);
        d = fmaf(tb.x, q4, d);
        myhd[j * KQT] = fmaf(-2.f, d, tb.y);
        myhi[j * KQT] = base + j;
    }
    float tau; int amax;
    {
        float bm = myhd[0]; int ba = 0;
        #pragma unroll
        for (int t = 1; t < KSEL; t++) {
            float hv = myhd[t * KQT];
            if (hv > bm) { bm = hv; ba = t; }
        }
        tau = bm; amax = ba;
    }

    int cnt = 0;

    #pragma unroll 1
    for (int ch = 0; ch < SLEN / CHUNK; ch++) {
        if (ch) {
            __syncthreads();               // all scans of prev chunk done
            const int mg = base + ch * CHUNK;
            st4[tid]       = __ldg(&tA4[mg + tid]);
            st2[tid]       = __ldg(&tB2[mg + tid]);
            st4[tid + 128] = __ldg(&tA4[mg + tid + 128]);
            st2[tid + 128] = __ldg(&tB2[mg + tid + 128]);
            __syncthreads();
        }
        const int mgc = base + ch * CHUNK;
        int k = (ch == 0) ? KSEL : 0;

        // align to window of 8 (only chunk 0: k=30 -> scalar 2)
        for (; k & 7; k++) {
            float4 ta = st4[k];
            float2 tb = st2[k];
            float d = ta.x * Qa.x;
            d = fmaf(ta.y, Qa.y, d);
            d = fmaf(ta.z, Qa.z, d);
            d = fmaf(ta.w, Qa.w, d);
            d = fmaf(tb.x, q4, d);
            float s = fmaf(-2.f, d, tb.y);
            if (s < tau) { myqs[cnt * KQT] = s; myqi[cnt * KQT] = mgc + k; cnt++; }
        }

        #pragma unroll 1
        for (; k < CHUNK; k += 8) {
            #pragma unroll
            for (int j = 0; j < 8; j++) {
                float4 ta = st4[k + j];
                float2 tb = st2[k + j];
                float d = ta.x * Qa.x;
                d = fmaf(ta.y, Qa.y, d);
                d = fmaf(ta.z, Qa.z, d);
                d = fmaf(ta.w, Qa.w, d);
                d = fmaf(tb.x, q4, d);
                float s = fmaf(-2.f, d, tb.y);
                if (s < tau) { myqs[cnt * KQT] = s; myqi[cnt * KQT] = mgc + k + j; cnt++; }
            }
            if (__any_sync(0xffffffffu, cnt > 8)) {
                for (int j = 0; j < cnt; j++) {
                    float v = myqs[j * KQT];
                    if (v < tau) {
                        // branchless replace-max insert
                        myhd[amax * KQT] = v;
                        myhi[amax * KQT] = myqi[j * KQT];
                        float bm = myhd[0]; int ba = 0;
                        #pragma unroll
                        for (int t = 1; t < KSEL; t++) {
                            float hv = myhd[t * KQT];
                            if (hv > bm) { bm = hv; ba = t; }
                        }
                        tau = bm; amax = ba;
                    }
                }
                cnt = 0;
            }
        }
    }
    for (int j = 0; j < cnt; j++) {
        float v = myqs[j * KQT];
        if (v < tau) {
            myhd[amax * KQT] = v;
            myhi[amax * KQT] = myqi[j * KQT];
            float bm = myhd[0]; int ba = 0;
            #pragma unroll
            for (int t = 1; t < KSEL; t++) {
                float hv = myhd[t * KQT];
                if (hv > bm) { bm = hv; ba = t; }
            }
            tau = bm; amax = ba;
        }
    }

    const size_t off = ((size_t)(b * NN + q) * NSLICE + sl) * KSEL;
    #pragma unroll
    for (int j = 0; j < KSEL; j++) {
        g_pd[off + j] = myhd[j * KQT];
        g_pi[off + j] = myhi[j * KQT];
    }
}

// ================================================================
// Phase 2b: merge 2x30 partials -> 30 smallest (tie: smaller index).
// (R4 verbatim; input lists unordered — rank-select doesn't care)
// ================================================================
__global__ void __launch_bounds__(256) knn_merge_kernel()
{
    const int wq   = (blockIdx.x << 3) + (threadIdx.x >> 5);
    const int lane = threadIdx.x & 31;

    const size_t off = (size_t)wq * (NSLICE * KSEL);
    float s0 = FINF, s1 = FINF;
    int   i0 = 0x7fffffff, i1 = 0x7fffffff;
    if (lane < KSEL) {
        s0 = g_pd[off + lane];         i0 = g_pi[off + lane];
        s1 = g_pd[off + KSEL + lane];  i1 = g_pi[off + KSEL + lane];
    }

    int r0 = 0, r1 = 0;
    #pragma unroll
    for (int j = 0; j < KSEL; j++) {
        float a  = __shfl_sync(0xffffffffu, s0, j);
        int   ai = __shfl_sync(0xffffffffu, i0, j);
        r0 += (a < s0) || (a == s0 && ai < i0);
        r1 += (a < s1) || (a == s1 && ai < i1);
        float c  = __shfl_sync(0xffffffffu, s1, j);
        int   ci = __shfl_sync(0xffffffffu, i1, j);
        r0 += (c < s0) || (c == s0 && ci < i0);
        r1 += (c < s1) || (c == s1 && ci < i1);
    }
    int* dst = g_nn + (size_t)wq * KSEL;
    if (lane < KSEL) {
        if (r0 < KSEL) dst[r0] = i0;
        if (r1 < KSEL) dst[r1] = i1;
    }
}

// ================================================================
// Phase 3: warp-per-query gather-max over 30 neighbors + 13x128 conv
// ================================================================
__global__ void __launch_bounds__(256) gather_kernel(
    const float* __restrict__ W_sem, const float* __restrict__ b_sem,
    float* __restrict__ p_out)
{
    const int warp = (blockIdx.x << 3) + (threadIdx.x >> 5);
    const int lane = threadIdx.x & 31;
    const int b = warp >> 12, n = warp & (NN - 1);

    const int* nnp = g_nn + (size_t)warp * KSEL;
    int myid = nnp[lane < KSEL ? lane : 0];

    const float* base = g_fsemT + ((size_t)b * NN) * CIN + (lane << 2);
    float4 vmax = make_float4(FNINF, FNINF, FNINF, FNINF);
    #pragma unroll 6
    for (int k = 0; k < KSEL; k++) {
        int j = __shfl_sync(0xffffffffu, myid, k);
        float4 v = *(const float4*)(base + (size_t)j * CIN);
        vmax.x = fmaxf(vmax.x, v.x);
        vmax.y = fmaxf(vmax.y, v.y);
        vmax.z = fmaxf(vmax.z, v.z);
        vmax.w = fmaxf(vmax.w, v.w);
    }

    float out[SEMOUT];
    #pragma unroll
    for (int o = 0; o < SEMOUT; o++) {
        float4 w = *(const float4*)(W_sem + o * CIN + (lane << 2));
        float a = w.x * vmax.x;
        a = fmaf(w.y, vmax.y, a);
        a = fmaf(w.z, vmax.z, a);
        a = fmaf(w.w, vmax.w, a);
        a += __shfl_xor_sync(0xffffffffu, a, 16);
        a += __shfl_xor_sync(0xffffffffu, a, 8);
        a += __shfl_xor_sync(0xffffffffu, a, 4);
        a += __shfl_xor_sync(0xffffffffu, a, 2);
        a += __shfl_xor_sync(0xffffffffu, a, 1);
        out[o] = a;
    }
    if (lane == 0) {
        float* dst = p_out + ((size_t)b * SEMOUT) * NN + n;
        #pragma unroll
        for (int o = 0; o < SEMOUT; o++)
            dst[(size_t)o * NN] = out[o] + b_sem[o];
    }
}

// ================================================================
extern "C" void kernel_launch(void* const* d_in, const int* in_sizes, int n_in,
                              void* d_out, int out_size)
{
    (void)in_sizes; (void)n_in; (void)out_size;
    const float* f_sem   = (const float*)d_in[0];
    const float* f_ins   = (const float*)d_in[1];
    const float* W_adapt = (const float*)d_in[2];
    const float* b_adapt = (const float*)d_in[3];
    const float* gamma   = (const float*)d_in[4];
    const float* beta    = (const float*)d_in[5];
    const float* W_ins   = (const float*)d_in[6];
    const float* b_ins   = (const float*)d_in[7];
    const float* W_sem   = (const float*)d_in[8];
    const float* b_sem   = (const float*)d_in[9];

    float* p_out = (float*)d_out;                       // [B,13,N]
    float* e_out = p_out + (size_t)BB * SEMOUT * NN;    // [B,5,N]

    const int smem1 = (32 * WPAD + 128 * XPAD + EOUT * 128 + 8) * 4;
    const int smem2 = CHUNK * 24 + (KSEL * KQT + QCAP * KQT) * 8;   // 52KB

    cudaFuncSetAttribute(phase1_kernel,      cudaFuncAttributeMaxDynamicSharedMemorySize, smem1);
    cudaFuncSetAttribute(knn_partial_kernel, cudaFuncAttributeMaxDynamicSharedMemorySize, smem2);

    phase1_kernel<<<BB * (NN / TP), 128, smem1>>>(
        f_sem, f_ins, W_adapt, b_adapt, gamma, beta, W_ins, b_ins, e_out);
    knn_partial_kernel<<<BB * (NN / KQT) * NSLICE, KQT, smem2>>>();
    knn_merge_kernel<<<BNN / 8, 256>>>();
    gather_kernel<<<BNN / 8, 256>>>(W_sem, b_sem, p_out);
}

// round 12
// speedup vs baseline: 1.5395x; 1.0165x over previous
#include <cuda_runtime.h>
#include <math_constants.h>

#define BB     8
#define NN     4096
#define BNN    (BB * NN)
#define CIN    128
#define EOUT   5
#define SEMOUT 13
#define KSEL   30
#define QCAP   16
#define TP     32
#define XPAD   36
#define WPAD   129
#define NSLICE 2
#define SLEN   (NN / NSLICE)
#define KQT    128
#define CHUNK  256

#define FINF  __int_as_float(0x7f800000)
#define FNINF __int_as_float(0xff800000)

// ---------------- scratch (static __device__, no runtime alloc) ----------------
__device__ float  g_fsemT[BNN * CIN];            // 16MB [b][n][c]
__device__ float4 g_tA[BNN];                     // (e0,e1,e2,e3)
__device__ float2 g_tB[BNN];                     // (e4, r=||e||^2)
__device__ int    g_nn[BNN * KSEL];              // final neighbor indices
__device__ float  g_pd[BNN * NSLICE * KSEL];     // partial dists
__device__ int    g_pi[BNN * NSLICE * KSEL];     // partial indices

// ================================================================
// Phase 1 — R4 verbatim
// ================================================================
__global__ void __launch_bounds__(128, 4) phase1_kernel(
    const float* __restrict__ f_sem, const float* __restrict__ f_ins,
    const float* __restrict__ W_adapt, const float* __restrict__ b_adapt,
    const float* __restrict__ gamma, const float* __restrict__ beta,
    const float* __restrict__ W_ins, const float* __restrict__ b_ins,
    float* __restrict__ e_out)
{
    extern __shared__ float sm1[];
    float* Ws = sm1;                      // 32*129
    float* Xs = sm1 + 32 * WPAD;          // 128*36 (reused as Ys)
    float* Wi = Xs + 128 * XPAD;          // 5*128 + 8

    const int tid = threadIdx.x;
    const int blk = blockIdx.x;
    const int b   = blk >> 7;
    const int n0  = (blk & 127) * TP;

    for (int i = tid; i < EOUT * 128; i += 128) Wi[i] = W_ins[i];
    if (tid < EOUT) Wi[EOUT * 128 + tid] = b_ins[tid];

    const float* fs = f_sem + ((size_t)b * CIN) * NN + n0;
    for (int i = tid; i < 128 * TP; i += 128) {
        int c = i >> 5, p = i & 31;
        Xs[c * XPAD + p] = fs[(size_t)c * NN + p];
    }
    __syncthreads();

    {
        float* dst = g_fsemT + ((size_t)(b * NN + n0)) * CIN + tid;
        #pragma unroll 4
        for (int p = 0; p < TP; p++)
            dst[(size_t)p * CIN] = Xs[tid * XPAD + p];
    }

    float acc[TP];
    #pragma unroll
    for (int p = 0; p < TP; p++) acc[p] = 0.f;

    #pragma unroll 1
    for (int ch = 0; ch < 4; ch++) {
        if (ch) __syncthreads();
        for (int i = tid; i < 32 * 128; i += 128) {
            int o  = i >> 5;
            int cc = i & 31;
            Ws[cc * WPAD + o] = W_adapt[o * 128 + ch * 32 + cc];
        }
        __syncthreads();

        #pragma unroll 4
        for (int cc = 0; cc < 32; cc++) {
            float w = Ws[cc * WPAD + tid];
            const float4* xr = (const float4*)(Xs + (ch * 32 + cc) * XPAD);
            #pragma unroll
            for (int p4 = 0; p4 < TP / 4; p4++) {
                float4 x = xr[p4];
                acc[4 * p4 + 0] = fmaf(w, x.x, acc[4 * p4 + 0]);
                acc[4 * p4 + 1] = fmaf(w, x.y, acc[4 * p4 + 1]);
                acc[4 * p4 + 2] = fmaf(w, x.z, acc[4 * p4 + 2]);
                acc[4 * p4 + 3] = fmaf(w, x.w, acc[4 * p4 + 3]);
            }
        }
    }

    const float g  = gamma[tid];
    const float bb = fmaf(g, b_adapt[tid], beta[tid]);
    const float* fi = f_ins + ((size_t)(b * CIN + tid)) * NN + n0;
    float y[TP];
    #pragma unroll
    for (int p = 0; p < TP; p++) {
        float a = fmaxf(fmaf(g, acc[p], bb), 0.f);
        y[p] = fi[p] + a;
    }
    __syncthreads();
    #pragma unroll
    for (int p = 0; p < TP; p++) Xs[tid * XPAD + p] = y[p];
    __syncthreads();

    if (tid < TP) {
        const int p = tid;
        float e[EOUT];
        #pragma unroll
        for (int j = 0; j < EOUT; j++) e[j] = Wi[EOUT * 128 + j];
        #pragma unroll 4
        for (int c = 0; c < 128; c++) {
            float x = Xs[c * XPAD + p];
            #pragma unroll
            for (int j = 0; j < EOUT; j++) e[j] = fmaf(Wi[j * 128 + c], x, e[j]);
        }
        float r = 0.f;
        #pragma unroll
        for (int j = 0; j < EOUT; j++) r = fmaf(e[j], e[j], r);
        const int n = n0 + p;
        float* eo = e_out + (size_t)b * EOUT * NN + n;
        #pragma unroll
        for (int j = 0; j < EOUT; j++) eo[(size_t)j * NN] = e[j];
        g_tA[b * NN + n] = make_float4(e[0], e[1], e[2], e[3]);
        g_tB[b * NN + n] = make_float2(e[4], r);
    }
}

// ================================================================
// Phase 2a: R10 structure; per-candidate accept made fully branchless:
// unconditional packed STS.64 to queue slot, cnt += predicate.
// ================================================================
__global__ void __launch_bounds__(KQT) knn_partial_kernel()
{
    extern __shared__ float smk[];
    float4* st4 = (float4*)smk;                            // CHUNK * 16B
    float2* st2 = (float2*)(st4 + CHUNK);                  // CHUNK * 8B
    float*  hd  = (float*)(st2 + CHUNK);                   // KSEL*KQT (unordered)
    int*    hi  = (int*)(hd + KSEL * KQT);                 // KSEL*KQT
    unsigned long long* qq = (unsigned long long*)(hi + KSEL * KQT);  // QCAP*KQT

    const int tid  = threadIdx.x;
    const int b    = blockIdx.x >> 6;              // 64 blocks per batch
    const int qblk = (blockIdx.x >> 1) & 31;
    const int sl   = blockIdx.x & 1;
    const int q    = (qblk << 7) + tid;
    const int base = sl * SLEN;

    const float4* tA4 = g_tA + b * NN;
    const float2* tB2 = g_tB + b * NN;

    const float4 Qa = __ldg(&tA4[q]);
    const float  q4 = __ldg(&tB2[q]).x;

    float* myhd = hd + tid; int* myhi = hi + tid;
    unsigned long long* myq = qq + tid;

    // stage chunk 0
    st4[tid]       = __ldg(&tA4[base + tid]);
    st2[tid]       = __ldg(&tB2[base + tid]);
    st4[tid + 128] = __ldg(&tA4[base + tid + 128]);
    st2[tid + 128] = __ldg(&tB2[base + tid + 128]);
    __syncthreads();

    // prefill 30 slots (unordered), then one branchless rescan for tau/amax
    #pragma unroll
    for (int j = 0; j < KSEL; j++) {
        float4 ta = st4[j];
        float2 tb = st2[j];
        float d = ta.x * Qa.x;
        d = fmaf(ta.y, Qa.y, d);
        d = fmaf(ta.z, Qa.z, d);
        d = fmaf(ta.w, Qa.w, d);
        d = fmaf(tb.x, q4, d);
        myhd[j * KQT] = fmaf(-2.f, d, tb.y);
        myhi[j * KQT] = base + j;
    }
    float tau; int amax;
    {
        float bm = myhd[0]; int ba = 0;
        #pragma unroll
        for (int t = 1; t < KSEL; t++) {
            float hv = myhd[t * KQT];
            bool g = hv > bm;
            bm = g ? hv : bm;
            ba = g ? t : ba;
        }
        tau = bm; amax = ba;
    }

    int cnt = 0;

    #pragma unroll 1
    for (int ch = 0; ch < SLEN / CHUNK; ch++) {
        if (ch) {
            __syncthreads();               // all scans of prev chunk done
            const int mg = base + ch * CHUNK;
            st4[tid]       = __ldg(&tA4[mg + tid]);
            st2[tid]       = __ldg(&tB2[mg + tid]);
            st4[tid + 128] = __ldg(&tA4[mg + tid + 128]);
            st2[tid + 128] = __ldg(&tB2[mg + tid + 128]);
            __syncthreads();
        }
        const int mgc = base + ch * CHUNK;
        int k = (ch == 0) ? KSEL : 0;

        // align to window of 8 (only chunk 0: k=30 -> scalar 2); branchless accept
        for (; k & 7; k++) {
            float4 ta = st4[k];
            float2 tb = st2[k];
            float d = ta.x * Qa.x;
            d = fmaf(ta.y, Qa.y, d);
            d = fmaf(ta.z, Qa.z, d);
            d = fmaf(ta.w, Qa.w, d);
            d = fmaf(tb.x, q4, d);
            float s = fmaf(-2.f, d, tb.y);
            myq[cnt * KQT] = ((unsigned long long)__float_as_uint(s) << 32)
                           | (unsigned)(mgc + k);
            cnt += (s < tau) ? 1 : 0;
        }

        #pragma unroll 1
        for (; k < CHUNK; k += 8) {
            #pragma unroll
            for (int j = 0; j < 8; j++) {
                float4 ta = st4[k + j];
                float2 tb = st2[k + j];
                float d = ta.x * Qa.x;
                d = fmaf(ta.y, Qa.y, d);
                d = fmaf(ta.z, Qa.z, d);
                d = fmaf(ta.w, Qa.w, d);
                d = fmaf(tb.x, q4, d);
                float s = fmaf(-2.f, d, tb.y);
                myq[cnt * KQT] = ((unsigned long long)__float_as_uint(s) << 32)
                               | (unsigned)(mgc + k + j);
                cnt += (s < tau) ? 1 : 0;
            }
            if (__any_sync(0xffffffffu, cnt > 8)) {
                for (int j = 0; j < cnt; j++) {
                    unsigned long long pk = myq[j * KQT];
                    float v = __uint_as_float((unsigned)(pk >> 32));
                    if (v < tau) {
                        myhd[amax * KQT] = v;
                        myhi[amax * KQT] = (int)(unsigned)pk;
                        float bm = myhd[0]; int ba = 0;
                        #pragma unroll
                        for (int t = 1; t < KSEL; t++) {
                            float hv = myhd[t * KQT];
                            bool g = hv > bm;
                            bm = g ? hv : bm;
                            ba = g ? t : ba;
                        }
                        tau = bm; amax = ba;
                    }
                }
                cnt = 0;
            }
        }
    }
    for (int j = 0; j < cnt; j++) {
        unsigned long long pk = myq[j * KQT];
        float v = __uint_as_float((unsigned)(pk >> 32));
        if (v < tau) {
            myhd[amax * KQT] = v;
            myhi[amax * KQT] = (int)(unsigned)pk;
            float bm = myhd[0]; int ba = 0;
            #pragma unroll
            for (int t = 1; t < KSEL; t++) {
                float hv = myhd[t * KQT];
                bool g = hv > bm;
                bm = g ? hv : bm;
                ba = g ? t : ba;
            }
            tau = bm; amax = ba;
        }
    }

    const size_t off = ((size_t)(b * NN + q) * NSLICE + sl) * KSEL;
    #pragma unroll
    for (int j = 0; j < KSEL; j++) {
        g_pd[off + j] = myhd[j * KQT];
        g_pi[off + j] = myhi[j * KQT];
    }
}

// ================================================================
// Phase 2b: merge 2x30 partials -> 30 smallest (tie: smaller index).
// (R4 verbatim; input lists unordered — rank-select doesn't care)
// ================================================================
__global__ void __launch_bounds__(256) knn_merge_kernel()
{
    const int wq   = (blockIdx.x << 3) + (threadIdx.x >> 5);
    const int lane = threadIdx.x & 31;

    const size_t off = (size_t)wq * (NSLICE * KSEL);
    float s0 = FINF, s1 = FINF;
    int   i0 = 0x7fffffff, i1 = 0x7fffffff;
    if (lane < KSEL) {
        s0 = g_pd[off + lane];         i0 = g_pi[off + lane];
        s1 = g_pd[off + KSEL + lane];  i1 = g_pi[off + KSEL + lane];
    }

    int r0 = 0, r1 = 0;
    #pragma unroll
    for (int j = 0; j < KSEL; j++) {
        float a  = __shfl_sync(0xffffffffu, s0, j);
        int   ai = __shfl_sync(0xffffffffu, i0, j);
        r0 += (a < s0) || (a == s0 && ai < i0);
        r1 += (a < s1) || (a == s1 && ai < i1);
        float c  = __shfl_sync(0xffffffffu, s1, j);
        int   ci = __shfl_sync(0xffffffffu, i1, j);
        r0 += (c < s0) || (c == s0 && ci < i0);
        r1 += (c < s1) || (c == s1 && ci < i1);
    }
    int* dst = g_nn + (size_t)wq * KSEL;
    if (lane < KSEL) {
        if (r0 < KSEL) dst[r0] = i0;
        if (r1 < KSEL) dst[r1] = i1;
    }
}

// ================================================================
// Phase 3: warp-per-query gather-max over 30 neighbors + 13x128 conv
// ================================================================
__global__ void __launch_bounds__(256) gather_kernel(
    const float* __restrict__ W_sem, const float* __restrict__ b_sem,
    float* __restrict__ p_out)
{
    const int warp = (blockIdx.x << 3) + (threadIdx.x >> 5);
    const int lane = threadIdx.x & 31;
    const int b = warp >> 12, n = warp & (NN - 1);

    const int* nnp = g_nn + (size_t)warp * KSEL;
    int myid = nnp[lane < KSEL ? lane : 0];

    const float* base = g_fsemT + ((size_t)b * NN) * CIN + (lane << 2);
    float4 vmax = make_float4(FNINF, FNINF, FNINF, FNINF);
    #pragma unroll 6
    for (int k = 0; k < KSEL; k++) {
        int j = __shfl_sync(0xffffffffu, myid, k);
        float4 v = *(const float4*)(base + (size_t)j * CIN);
        vmax.x = fmaxf(vmax.x, v.x);
        vmax.y = fmaxf(vmax.y, v.y);
        vmax.z = fmaxf(vmax.z, v.z);
        vmax.w = fmaxf(vmax.w, v.w);
    }

    float out[SEMOUT];
    #pragma unroll
    for (int o = 0; o < SEMOUT; o++) {
        float4 w = *(const float4*)(W_sem + o * CIN + (lane << 2));
        float a = w.x * vmax.x;
        a = fmaf(w.y, vmax.y, a);
        a = fmaf(w.z, vmax.z, a);
        a = fmaf(w.w, vmax.w, a);
        a += __shfl_xor_sync(0xffffffffu, a, 16);
        a += __shfl_xor_sync(0xffffffffu, a, 8);
        a += __shfl_xor_sync(0xffffffffu, a, 4);
        a += __shfl_xor_sync(0xffffffffu, a, 2);
        a += __shfl_xor_sync(0xffffffffu, a, 1);
        out[o] = a;
    }
    if (lane == 0) {
        float* dst = p_out + ((size_t)b * SEMOUT) * NN + n;
        #pragma unroll
        for (int o = 0; o < SEMOUT; o++)
            dst[(size_t)o * NN] = out[o] + b_sem[o];
    }
}

// ================================================================
extern "C" void kernel_launch(void* const* d_in, const int* in_sizes, int n_in,
                              void* d_out, int out_size)
{
    (void)in_sizes; (void)n_in; (void)out_size;
    const float* f_sem   = (const float*)d_in[0];
    const float* f_ins   = (const float*)d_in[1];
    const float* W_adapt = (const float*)d_in[2];
    const float* b_adapt = (const float*)d_in[3];
    const float* gamma   = (const float*)d_in[4];
    const float* beta    = (const float*)d_in[5];
    const float* W_ins   = (const float*)d_in[6];
    const float* b_ins   = (const float*)d_in[7];
    const float* W_sem   = (const float*)d_in[8];
    const float* b_sem   = (const float*)d_in[9];

    float* p_out = (float*)d_out;                       // [B,13,N]
    float* e_out = p_out + (size_t)BB * SEMOUT * NN;    // [B,5,N]

    const int smem1 = (32 * WPAD + 128 * XPAD + EOUT * 128 + 8) * 4;
    const int smem2 = CHUNK * 24 + KSEL * KQT * 8 + QCAP * KQT * 8;   // 52KB

    cudaFuncSetAttribute(phase1_kernel,      cudaFuncAttributeMaxDynamicSharedMemorySize, smem1);
    cudaFuncSetAttribute(knn_partial_kernel, cudaFuncAttributeMaxDynamicSharedMemorySize, smem2);

    phase1_kernel<<<BB * (NN / TP), 128, smem1>>>(
        f_sem, f_ins, W_adapt, b_adapt, gamma, beta, W_ins, b_ins, e_out);
    knn_partial_kernel<<<BB * (NN / KQT) * NSLICE, KQT, smem2>>>();
    knn_merge_kernel<<<BNN / 8, 256>>>();
    gather_kernel<<<BNN / 8, 256>>>(W_sem, b_sem, p_out);
}

// round 13
// speedup vs baseline: 1.5418x; 1.0015x over previous
#include <cuda_runtime.h>
#include <math_constants.h>

#define BB     8
#define NN     4096
#define BNN    (BB * NN)
#define CIN    128
#define EOUT   5
#define SEMOUT 13
#define KSEL   30
#define QCAP   16
#define TP     32
#define XPAD   36
#define NSLICE 2
#define SLEN   (NN / NSLICE)
#define KQT    128
#define CHUNK  256

#define FINF  __int_as_float(0x7f800000)
#define FNINF __int_as_float(0xff800000)

// ---------------- scratch (static __device__, no runtime alloc) ----------------
__device__ float  g_fsemT[BNN * CIN];            // 16MB [b][n][c]
__device__ float  g_WT[CIN * CIN];               // W_adapt^T: [cin][cout]
__device__ float4 g_tA[BNN];                     // (e0,e1,e2,e3)
__device__ float2 g_tB[BNN];                     // (e4, r=||e||^2)
__device__ int    g_nn[BNN * KSEL];              // final neighbor indices
__device__ float  g_pd[BNN * NSLICE * KSEL];     // partial dists
__device__ int    g_pi[BNN * NSLICE * KSEL];     // partial indices

// ================================================================
// Phase 0: transpose W_adapt once (64KB, stays L2-resident)
// ================================================================
__global__ void wt_kernel(const float* __restrict__ W_adapt)
{
    const int i = blockIdx.x * 256 + threadIdx.x;   // i = c*128 + o
    const int c = i >> 7, o = i & 127;
    g_WT[i] = W_adapt[o * 128 + c];
}

// ================================================================
// Phase 1: same math as R4; W read straight from g_WT (no smem staging)
// ================================================================
__global__ void __launch_bounds__(128, 6) phase1_kernel(
    const float* __restrict__ f_sem, const float* __restrict__ f_ins,
    const float* __restrict__ b_adapt,
    const float* __restrict__ gamma, const float* __restrict__ beta,
    const float* __restrict__ W_ins, const float* __restrict__ b_ins,
    float* __restrict__ e_out)
{
    extern __shared__ float sm1[];
    float* Xs = sm1;                      // 128*36 (reused as Ys)
    float* Wi = Xs + 128 * XPAD;          // 5*128 + 8

    const int tid = threadIdx.x;
    const int blk = blockIdx.x;
    const int b   = blk >> 7;
    const int n0  = (blk & 127) * TP;

    for (int i = tid; i < EOUT * 128; i += 128) Wi[i] = W_ins[i];
    if (tid < EOUT) Wi[EOUT * 128 + tid] = b_ins[tid];

    const float* fs = f_sem + ((size_t)b * CIN) * NN + n0;
    for (int i = tid; i < 128 * TP; i += 128) {
        int c = i >> 5, p = i & 31;
        Xs[c * XPAD + p] = fs[(size_t)c * NN + p];
    }
    __syncthreads();

    {
        float* dst = g_fsemT + ((size_t)(b * NN + n0)) * CIN + tid;
        #pragma unroll 4
        for (int p = 0; p < TP; p++)
            dst[(size_t)p * CIN] = Xs[tid * XPAD + p];
    }

    float acc[TP];
    #pragma unroll
    for (int p = 0; p < TP; p++) acc[p] = 0.f;

    const float* wt = g_WT + tid;
    #pragma unroll 4
    for (int c = 0; c < CIN; c++) {
        float w = __ldg(wt + c * CIN);
        const float4* xr = (const float4*)(Xs + c * XPAD);
        #pragma unroll
        for (int p4 = 0; p4 < TP / 4; p4++) {
            float4 x = xr[p4];
            acc[4 * p4 + 0] = fmaf(w, x.x, acc[4 * p4 + 0]);
            acc[4 * p4 + 1] = fmaf(w, x.y, acc[4 * p4 + 1]);
            acc[4 * p4 + 2] = fmaf(w, x.z, acc[4 * p4 + 2]);
            acc[4 * p4 + 3] = fmaf(w, x.w, acc[4 * p4 + 3]);
        }
    }

    const float g  = gamma[tid];
    const float bb = fmaf(g, b_adapt[tid], beta[tid]);
    const float* fi = f_ins + ((size_t)(b * CIN + tid)) * NN + n0;
    float y[TP];
    #pragma unroll
    for (int p = 0; p < TP; p++) {
        float a = fmaxf(fmaf(g, acc[p], bb), 0.f);
        y[p] = fi[p] + a;
    }
    __syncthreads();
    #pragma unroll
    for (int p = 0; p < TP; p++) Xs[tid * XPAD + p] = y[p];
    __syncthreads();

    if (tid < TP) {
        const int p = tid;
        float e[EOUT];
        #pragma unroll
        for (int j = 0; j < EOUT; j++) e[j] = Wi[EOUT * 128 + j];
        #pragma unroll 4
        for (int c = 0; c < 128; c++) {
            float x = Xs[c * XPAD + p];
            #pragma unroll
            for (int j = 0; j < EOUT; j++) e[j] = fmaf(Wi[j * 128 + c], x, e[j]);
        }
        float r = 0.f;
        #pragma unroll
        for (int j = 0; j < EOUT; j++) r = fmaf(e[j], e[j], r);
        const int n = n0 + p;
        float* eo = e_out + (size_t)b * EOUT * NN + n;
        #pragma unroll
        for (int j = 0; j < EOUT; j++) eo[(size_t)j * NN] = e[j];
        g_tA[b * NN + n] = make_float4(e[0], e[1], e[2], e[3]);
        g_tB[b * NN + n] = make_float2(e[4], r);
    }
}

// ================================================================
// Phase 2a — R12 verbatim (branchless accept, replace-max kept-set)
// ================================================================
__global__ void __launch_bounds__(KQT) knn_partial_kernel()
{
    extern __shared__ float smk[];
    float4* st4 = (float4*)smk;                            // CHUNK * 16B
    float2* st2 = (float2*)(st4 + CHUNK);                  // CHUNK * 8B
    float*  hd  = (float*)(st2 + CHUNK);                   // KSEL*KQT (unordered)
    int*    hi  = (int*)(hd + KSEL * KQT);                 // KSEL*KQT
    unsigned long long* qq = (unsigned long long*)(hi + KSEL * KQT);  // QCAP*KQT

    const int tid  = threadIdx.x;
    const int b    = blockIdx.x >> 6;              // 64 blocks per batch
    const int qblk = (blockIdx.x >> 1) & 31;
    const int sl   = blockIdx.x & 1;
    const int q    = (qblk << 7) + tid;
    const int base = sl * SLEN;

    const float4* tA4 = g_tA + b * NN;
    const float2* tB2 = g_tB + b * NN;

    const float4 Qa = __ldg(&tA4[q]);
    const float  q4 = __ldg(&tB2[q]).x;

    float* myhd = hd + tid; int* myhi = hi + tid;
    unsigned long long* myq = qq + tid;

    st4[tid]       = __ldg(&tA4[base + tid]);
    st2[tid]       = __ldg(&tB2[base + tid]);
    st4[tid + 128] = __ldg(&tA4[base + tid + 128]);
    st2[tid + 128] = __ldg(&tB2[base + tid + 128]);
    __syncthreads();

    #pragma unroll
    for (int j = 0; j < KSEL; j++) {
        float4 ta = st4[j];
        float2 tb = st2[j];
        float d = ta.x * Qa.x;
        d = fmaf(ta.y, Qa.y, d);
        d = fmaf(ta.z, Qa.z, d);
        d = fmaf(ta.w, Qa.w, d);
        d = fmaf(tb.x, q4, d);
        myhd[j * KQT] = fmaf(-2.f, d, tb.y);
        myhi[j * KQT] = base + j;
    }
    float tau; int amax;
    {
        float bm = myhd[0]; int ba = 0;
        #pragma unroll
        for (int t = 1; t < KSEL; t++) {
            float hv = myhd[t * KQT];
            bool g = hv > bm;
            bm = g ? hv : bm;
            ba = g ? t : ba;
        }
        tau = bm; amax = ba;
    }

    int cnt = 0;

    #pragma unroll 1
    for (int ch = 0; ch < SLEN / CHUNK; ch++) {
        if (ch) {
            __syncthreads();
            const int mg = base + ch * CHUNK;
            st4[tid]       = __ldg(&tA4[mg + tid]);
            st2[tid]       = __ldg(&tB2[mg + tid]);
            st4[tid + 128] = __ldg(&tA4[mg + tid + 128]);
            st2[tid + 128] = __ldg(&tB2[mg + tid + 128]);
            __syncthreads();
        }
        const int mgc = base + ch * CHUNK;
        int k = (ch == 0) ? KSEL : 0;

        for (; k & 7; k++) {
            float4 ta = st4[k];
            float2 tb = st2[k];
            float d = ta.x * Qa.x;
            d = fmaf(ta.y, Qa.y, d);
            d = fmaf(ta.z, Qa.z, d);
            d = fmaf(ta.w, Qa.w, d);
            d = fmaf(tb.x, q4, d);
            float s = fmaf(-2.f, d, tb.y);
            myq[cnt * KQT] = ((unsigned long long)__float_as_uint(s) << 32)
                           | (unsigned)(mgc + k);
            cnt += (s < tau) ? 1 : 0;
        }

        #pragma unroll 1
        for (; k < CHUNK; k += 8) {
            #pragma unroll
            for (int j = 0; j < 8; j++) {
                float4 ta = st4[k + j];
                float2 tb = st2[k + j];
                float d = ta.x * Qa.x;
                d = fmaf(ta.y, Qa.y, d);
                d = fmaf(ta.z, Qa.z, d);
                d = fmaf(ta.w, Qa.w, d);
                d = fmaf(tb.x, q4, d);
                float s = fmaf(-2.f, d, tb.y);
                myq[cnt * KQT] = ((unsigned long long)__float_as_uint(s) << 32)
                               | (unsigned)(mgc + k + j);
                cnt += (s < tau) ? 1 : 0;
            }
            if (__any_sync(0xffffffffu, cnt > 8)) {
                for (int j = 0; j < cnt; j++) {
                    unsigned long long pk = myq[j * KQT];
                    float v = __uint_as_float((unsigned)(pk >> 32));
                    if (v < tau) {
                        myhd[amax * KQT] = v;
                        myhi[amax * KQT] = (int)(unsigned)pk;
                        float bm = myhd[0]; int ba = 0;
                        #pragma unroll
                        for (int t = 1; t < KSEL; t++) {
                            float hv = myhd[t * KQT];
                            bool g = hv > bm;
                            bm = g ? hv : bm;
                            ba = g ? t : ba;
                        }
                        tau = bm; amax = ba;
                    }
                }
                cnt = 0;
            }
        }
    }
    for (int j = 0; j < cnt; j++) {
        unsigned long long pk = myq[j * KQT];
        float v = __uint_as_float((unsigned)(pk >> 32));
        if (v < tau) {
            myhd[amax * KQT] = v;
            myhi[amax * KQT] = (int)(unsigned)pk;
            float bm = myhd[0]; int ba = 0;
            #pragma unroll
            for (int t = 1; t < KSEL; t++) {
                float hv = myhd[t * KQT];
                bool g = hv > bm;
                bm = g ? hv : bm;
                ba = g ? t : ba;
            }
            tau = bm; amax = ba;
        }
    }

    const size_t off = ((size_t)(b * NN + q) * NSLICE + sl) * KSEL;
    #pragma unroll
    for (int j = 0; j < KSEL; j++) {
        g_pd[off + j] = myhd[j * KQT];
        g_pi[off + j] = myhi[j * KQT];
    }
}

// ================================================================
// Phase 2b — R4 verbatim
// ================================================================
__global__ void __launch_bounds__(256) knn_merge_kernel()
{
    const int wq   = (blockIdx.x << 3) + (threadIdx.x >> 5);
    const int lane = threadIdx.x & 31;

    const size_t off = (size_t)wq * (NSLICE * KSEL);
    float s0 = FINF, s1 = FINF;
    int   i0 = 0x7fffffff, i1 = 0x7fffffff;
    if (lane < KSEL) {
        s0 = g_pd[off + lane];         i0 = g_pi[off + lane];
        s1 = g_pd[off + KSEL + lane];  i1 = g_pi[off + KSEL + lane];
    }

    int r0 = 0, r1 = 0;
    #pragma unroll
    for (int j = 0; j < KSEL; j++) {
        float a  = __shfl_sync(0xffffffffu, s0, j);
        int   ai = __shfl_sync(0xffffffffu, i0, j);
        r0 += (a < s0) || (a == s0 && ai < i0);
        r1 += (a < s1) || (a == s1 && ai < i1);
        float c  = __shfl_sync(0xffffffffu, s1, j);
        int   ci = __shfl_sync(0xffffffffu, i1, j);
        r0 += (c < s0) || (c == s0 && ci < i0);
        r1 += (c < s1) || (c == s1 && ci < i1);
    }
    int* dst = g_nn + (size_t)wq * KSEL;
    if (lane < KSEL) {
        if (r0 < KSEL) dst[r0] = i0;
        if (r1 < KSEL) dst[r1] = i1;
    }
}

// ================================================================
// Phase 3 — R4 verbatim
// ================================================================
__global__ void __launch_bounds__(256) gather_kernel(
    const float* __restrict__ W_sem, const float* __restrict__ b_sem,
    float* __restrict__ p_out)
{
    const int warp = (blockIdx.x << 3) + (threadIdx.x >> 5);
    const int lane = threadIdx.x & 31;
    const int b = warp >> 12, n = warp & (NN - 1);

    const int* nnp = g_nn + (size_t)warp * KSEL;
    int myid = nnp[lane < KSEL ? lane : 0];

    const float* base = g_fsemT + ((size_t)b * NN) * CIN + (lane << 2);
    float4 vmax = make_float4(FNINF, FNINF, FNINF, FNINF);
    #pragma unroll 6
    for (int k = 0; k < KSEL; k++) {
        int j = __shfl_sync(0xffffffffu, myid, k);
        float4 v = *(const float4*)(base + (size_t)j * CIN);
        vmax.x = fmaxf(vmax.x, v.x);
        vmax.y = fmaxf(vmax.y, v.y);
        vmax.z = fmaxf(vmax.z, v.z);
        vmax.w = fmaxf(vmax.w, v.w);
    }

    float out[SEMOUT];
    #pragma unroll
    for (int o = 0; o < SEMOUT; o++) {
        float4 w = *(const float4*)(W_sem + o * CIN + (lane << 2));
        float a = w.x * vmax.x;
        a = fmaf(w.y, vmax.y, a);
        a = fmaf(w.z, vmax.z, a);
        a = fmaf(w.w, vmax.w, a);
        a += __shfl_xor_sync(0xffffffffu, a, 16);
        a += __shfl_xor_sync(0xffffffffu, a, 8);
        a += __shfl_xor_sync(0xffffffffu, a, 4);
        a += __shfl_xor_sync(0xffffffffu, a, 2);
        a += __shfl_xor_sync(0xffffffffu, a, 1);
        out[o] = a;
    }
    if (lane == 0) {
        float* dst = p_out + ((size_t)b * SEMOUT) * NN + n;
        #pragma unroll
        for (int o = 0; o < SEMOUT; o++)
            dst[(size_t)o * NN] = out[o] + b_sem[o];
    }
}

// ================================================================
extern "C" void kernel_launch(void* const* d_in, const int* in_sizes, int n_in,
                              void* d_out, int out_size)
{
    (void)in_sizes; (void)n_in; (void)out_size;
    const float* f_sem   = (const float*)d_in[0];
    const float* f_ins   = (const float*)d_in[1];
    const float* W_adapt = (const float*)d_in[2];
    const float* b_adapt = (const float*)d_in[3];
    const float* gamma   = (const float*)d_in[4];
    const float* beta    = (const float*)d_in[5];
    const float* W_ins   = (const float*)d_in[6];
    const float* b_ins   = (const float*)d_in[7];
    const float* W_sem   = (const float*)d_in[8];
    const float* b_sem   = (const float*)d_in[9];

    float* p_out = (float*)d_out;                       // [B,13,N]
    float* e_out = p_out + (size_t)BB * SEMOUT * NN;    // [B,5,N]

    const int smem1 = (128 * XPAD + EOUT * 128 + 8) * 4;               // ~21KB
    const int smem2 = CHUNK * 24 + KSEL * KQT * 8 + QCAP * KQT * 8;    // 52KB

    cudaFuncSetAttribute(phase1_kernel,      cudaFuncAttributeMaxDynamicSharedMemorySize, smem1);
    cudaFuncSetAttribute(knn_partial_kernel, cudaFuncAttributeMaxDynamicSharedMemorySize, smem2);

    wt_kernel<<<CIN * CIN / 256, 256>>>(W_adapt);
    phase1_kernel<<<BB * (NN / TP), 128, smem1>>>(
        f_sem, f_ins, b_adapt, gamma, beta, W_ins, b_ins, e_out);
    knn_partial_kernel<<<BB * (NN / KQT) * NSLICE, KQT, smem2>>>();
    knn_merge_kernel<<<BNN / 8, 256>>>();
    gather_kernel<<<BNN / 8, 256>>>(W_sem, b_sem, p_out);
}

// round 14
// speedup vs baseline: 1.6052x; 1.0411x over previous
#include <cuda_runtime.h>
#include <math_constants.h>

#define BB     8
#define NN     4096
#define BNN    (BB * NN)
#define CIN    128
#define EOUT   5
#define SEMOUT 13
#define KSEL   30
#define QCAP   16
#define TP     32
#define XPAD   36
#define NSLICE 2
#define SLEN   (NN / NSLICE)
#define KQT    128
#define CHUNK  256

#define FINF  __int_as_float(0x7f800000)
#define FNINF __int_as_float(0xff800000)

// ---------------- scratch (static __device__, no runtime alloc) ----------------
__device__ float  g_fsemT[BNN * CIN];            // 16MB [b][n][c]
__device__ float  g_WT[CIN * CIN];               // W_adapt^T: [cin][cout]
__device__ float4 g_tA[BNN];                     // (e0,e1,e2,e3)
__device__ float2 g_tB[BNN];                     // (e4, r=||e||^2)
__device__ float  g_pd[BNN * NSLICE * KSEL];     // partial dists
__device__ int    g_pi[BNN * NSLICE * KSEL];     // partial indices

// ================================================================
// Phase 0: transpose W_adapt once (64KB, stays L2-resident)
// ================================================================
__global__ void wt_kernel(const float* __restrict__ W_adapt)
{
    const int i = blockIdx.x * 256 + threadIdx.x;   // i = c*128 + o
    const int c = i >> 7, o = i & 127;
    g_WT[i] = W_adapt[o * 128 + c];
}

// ================================================================
// Phase 1 — R12 verbatim
// ================================================================
__global__ void __launch_bounds__(128, 6) phase1_kernel(
    const float* __restrict__ f_sem, const float* __restrict__ f_ins,
    const float* __restrict__ b_adapt,
    const float* __restrict__ gamma, const float* __restrict__ beta,
    const float* __restrict__ W_ins, const float* __restrict__ b_ins,
    float* __restrict__ e_out)
{
    extern __shared__ float sm1[];
    float* Xs = sm1;                      // 128*36 (reused as Ys)
    float* Wi = Xs + 128 * XPAD;          // 5*128 + 8

    const int tid = threadIdx.x;
    const int blk = blockIdx.x;
    const int b   = blk >> 7;
    const int n0  = (blk & 127) * TP;

    for (int i = tid; i < EOUT * 128; i += 128) Wi[i] = W_ins[i];
    if (tid < EOUT) Wi[EOUT * 128 + tid] = b_ins[tid];

    const float* fs = f_sem + ((size_t)b * CIN) * NN + n0;
    for (int i = tid; i < 128 * TP; i += 128) {
        int c = i >> 5, p = i & 31;
        Xs[c * XPAD + p] = fs[(size_t)c * NN + p];
    }
    __syncthreads();

    {
        float* dst = g_fsemT + ((size_t)(b * NN + n0)) * CIN + tid;
        #pragma unroll 4
        for (int p = 0; p < TP; p++)
            dst[(size_t)p * CIN] = Xs[tid * XPAD + p];
    }

    float acc[TP];
    #pragma unroll
    for (int p = 0; p < TP; p++) acc[p] = 0.f;

    const float* wt = g_WT + tid;
    #pragma unroll 4
    for (int c = 0; c < CIN; c++) {
        float w = __ldg(wt + c * CIN);
        const float4* xr = (const float4*)(Xs + c * XPAD);
        #pragma unroll
        for (int p4 = 0; p4 < TP / 4; p4++) {
            float4 x = xr[p4];
            acc[4 * p4 + 0] = fmaf(w, x.x, acc[4 * p4 + 0]);
            acc[4 * p4 + 1] = fmaf(w, x.y, acc[4 * p4 + 1]);
            acc[4 * p4 + 2] = fmaf(w, x.z, acc[4 * p4 + 2]);
            acc[4 * p4 + 3] = fmaf(w, x.w, acc[4 * p4 + 3]);
        }
    }

    const float g  = gamma[tid];
    const float bb = fmaf(g, b_adapt[tid], beta[tid]);
    const float* fi = f_ins + ((size_t)(b * CIN + tid)) * NN + n0;
    float y[TP];
    #pragma unroll
    for (int p = 0; p < TP; p++) {
        float a = fmaxf(fmaf(g, acc[p], bb), 0.f);
        y[p] = fi[p] + a;
    }
    __syncthreads();
    #pragma unroll
    for (int p = 0; p < TP; p++) Xs[tid * XPAD + p] = y[p];
    __syncthreads();

    if (tid < TP) {
        const int p = tid;
        float e[EOUT];
        #pragma unroll
        for (int j = 0; j < EOUT; j++) e[j] = Wi[EOUT * 128 + j];
        #pragma unroll 4
        for (int c = 0; c < 128; c++) {
            float x = Xs[c * XPAD + p];
            #pragma unroll
            for (int j = 0; j < EOUT; j++) e[j] = fmaf(Wi[j * 128 + c], x, e[j]);
        }
        float r = 0.f;
        #pragma unroll
        for (int j = 0; j < EOUT; j++) r = fmaf(e[j], e[j], r);
        const int n = n0 + p;
        float* eo = e_out + (size_t)b * EOUT * NN + n;
        #pragma unroll
        for (int j = 0; j < EOUT; j++) eo[(size_t)j * NN] = e[j];
        g_tA[b * NN + n] = make_float4(e[0], e[1], e[2], e[3]);
        g_tB[b * NN + n] = make_float2(e[4], r);
    }
}

// ================================================================
// Phase 2a — R12 verbatim (branchless accept, replace-max kept-set)
// ================================================================
__global__ void __launch_bounds__(KQT) knn_partial_kernel()
{
    extern __shared__ float smk[];
    float4* st4 = (float4*)smk;                            // CHUNK * 16B
    float2* st2 = (float2*)(st4 + CHUNK);                  // CHUNK * 8B
    float*  hd  = (float*)(st2 + CHUNK);                   // KSEL*KQT (unordered)
    int*    hi  = (int*)(hd + KSEL * KQT);                 // KSEL*KQT
    unsigned long long* qq = (unsigned long long*)(hi + KSEL * KQT);  // QCAP*KQT

    const int tid  = threadIdx.x;
    const int b    = blockIdx.x >> 6;              // 64 blocks per batch
    const int qblk = (blockIdx.x >> 1) & 31;
    const int sl   = blockIdx.x & 1;
    const int q    = (qblk << 7) + tid;
    const int base = sl * SLEN;

    const float4* tA4 = g_tA + b * NN;
    const float2* tB2 = g_tB + b * NN;

    const float4 Qa = __ldg(&tA4[q]);
    const float  q4 = __ldg(&tB2[q]).x;

    float* myhd = hd + tid; int* myhi = hi + tid;
    unsigned long long* myq = qq + tid;

    st4[tid]       = __ldg(&tA4[base + tid]);
    st2[tid]       = __ldg(&tB2[base + tid]);
    st4[tid + 128] = __ldg(&tA4[base + tid + 128]);
    st2[tid + 128] = __ldg(&tB2[base + tid + 128]);
    __syncthreads();

    #pragma unroll
    for (int j = 0; j < KSEL; j++) {
        float4 ta = st4[j];
        float2 tb = st2[j];
        float d = ta.x * Qa.x;
        d = fmaf(ta.y, Qa.y, d);
        d = fmaf(ta.z, Qa.z, d);
        d = fmaf(ta.w, Qa.w, d);
        d = fmaf(tb.x, q4, d);
        myhd[j * KQT] = fmaf(-2.f, d, tb.y);
        myhi[j * KQT] = base + j;
    }
    float tau; int amax;
    {
        float bm = myhd[0]; int ba = 0;
        #pragma unroll
        for (int t = 1; t < KSEL; t++) {
            float hv = myhd[t * KQT];
            bool g = hv > bm;
            bm = g ? hv : bm;
            ba = g ? t : ba;
        }
        tau = bm; amax = ba;
    }

    int cnt = 0;

    #pragma unroll 1
    for (int ch = 0; ch < SLEN / CHUNK; ch++) {
        if (ch) {
            __syncthreads();
            const int mg = base + ch * CHUNK;
            st4[tid]       = __ldg(&tA4[mg + tid]);
            st2[tid]       = __ldg(&tB2[mg + tid]);
            st4[tid + 128] = __ldg(&tA4[mg + tid + 128]);
            st2[tid + 128] = __ldg(&tB2[mg + tid + 128]);
            __syncthreads();
        }
        const int mgc = base + ch * CHUNK;
        int k = (ch == 0) ? KSEL : 0;

        for (; k & 7; k++) {
            float4 ta = st4[k];
            float2 tb = st2[k];
            float d = ta.x * Qa.x;
            d = fmaf(ta.y, Qa.y, d);
            d = fmaf(ta.z, Qa.z, d);
            d = fmaf(ta.w, Qa.w, d);
            d = fmaf(tb.x, q4, d);
            float s = fmaf(-2.f, d, tb.y);
            myq[cnt * KQT] = ((unsigned long long)__float_as_uint(s) << 32)
                           | (unsigned)(mgc + k);
            cnt += (s < tau) ? 1 : 0;
        }

        #pragma unroll 1
        for (; k < CHUNK; k += 8) {
            #pragma unroll
            for (int j = 0; j < 8; j++) {
                float4 ta = st4[k + j];
                float2 tb = st2[k + j];
                float d = ta.x * Qa.x;
                d = fmaf(ta.y, Qa.y, d);
                d = fmaf(ta.z, Qa.z, d);
                d = fmaf(ta.w, Qa.w, d);
                d = fmaf(tb.x, q4, d);
                float s = fmaf(-2.f, d, tb.y);
                myq[cnt * KQT] = ((unsigned long long)__float_as_uint(s) << 32)
                               | (unsigned)(mgc + k + j);
                cnt += (s < tau) ? 1 : 0;
            }
            if (__any_sync(0xffffffffu, cnt > 8)) {
                for (int j = 0; j < cnt; j++) {
                    unsigned long long pk = myq[j * KQT];
                    float v = __uint_as_float((unsigned)(pk >> 32));
                    if (v < tau) {
                        myhd[amax * KQT] = v;
                        myhi[amax * KQT] = (int)(unsigned)pk;
                        float bm = myhd[0]; int ba = 0;
                        #pragma unroll
                        for (int t = 1; t < KSEL; t++) {
                            float hv = myhd[t * KQT];
                            bool g = hv > bm;
                            bm = g ? hv : bm;
                            ba = g ? t : ba;
                        }
                        tau = bm; amax = ba;
                    }
                }
                cnt = 0;
            }
        }
    }
    for (int j = 0; j < cnt; j++) {
        unsigned long long pk = myq[j * KQT];
        float v = __uint_as_float((unsigned)(pk >> 32));
        if (v < tau) {
            myhd[amax * KQT] = v;
            myhi[amax * KQT] = (int)(unsigned)pk;
            float bm = myhd[0]; int ba = 0;
            #pragma unroll
            for (int t = 1; t < KSEL; t++) {
                float hv = myhd[t * KQT];
                bool g = hv > bm;
                bm = g ? hv : bm;
                ba = g ? t : ba;
            }
            tau = bm; amax = ba;
        }
    }

    const size_t off = ((size_t)(b * NN + q) * NSLICE + sl) * KSEL;
    #pragma unroll
    for (int j = 0; j < KSEL; j++) {
        g_pd[off + j] = myhd[j * KQT];
        g_pi[off + j] = myhi[j * KQT];
    }
}

// ================================================================
// Phase 3: fused merge + gather. Warp per query:
//  1) rank-select 30 smallest of the 2x30 partials (merge, verbatim logic)
//  2) gather-max over the selected 30 neighbors + 13x128 conv
// ================================================================
__global__ void __launch_bounds__(256) gather_kernel(
    const float* __restrict__ W_sem, const float* __restrict__ b_sem,
    float* __restrict__ p_out)
{
    __shared__ int sel[8][32];

    const int w    = threadIdx.x >> 5;
    const int warp = (blockIdx.x << 3) + w;
    const int lane = threadIdx.x & 31;
    const int b = warp >> 12, n = warp & (NN - 1);

    // ---- merge (R4 rank-select, verbatim semantics) ----
    const size_t off = (size_t)warp * (NSLICE * KSEL);
    float s0 = FINF, s1 = FINF;
    int   i0 = 0x7fffffff, i1 = 0x7fffffff;
    if (lane < KSEL) {
        s0 = g_pd[off + lane];         i0 = g_pi[off + lane];
        s1 = g_pd[off + KSEL + lane];  i1 = g_pi[off + KSEL + lane];
    }

    int r0 = 0, r1 = 0;
    #pragma unroll
    for (int j = 0; j < KSEL; j++) {
        float a  = __shfl_sync(0xffffffffu, s0, j);
        int   ai = __shfl_sync(0xffffffffu, i0, j);
        r0 += (a < s0) || (a == s0 && ai < i0);
        r1 += (a < s1) || (a == s1 && ai < i1);
        float c  = __shfl_sync(0xffffffffu, s1, j);
        int   ci = __shfl_sync(0xffffffffu, i1, j);
        r0 += (c < s0) || (c == s0 && ci < i0);
        r1 += (c < s1) || (c == s1 && ci < i1);
    }
    if (lane < KSEL) {
        if (r0 < KSEL) sel[w][r0] = i0;
        if (r1 < KSEL) sel[w][r1] = i1;
    }
    __syncwarp();

    // ---- gather-max + conv (R4 verbatim) ----
    int myid = sel[w][lane < KSEL ? lane : 0];

    const float* base = g_fsemT + ((size_t)b * NN) * CIN + (lane << 2);
    float4 vmax = make_float4(FNINF, FNINF, FNINF, FNINF);
    #pragma unroll 6
    for (int k = 0; k < KSEL; k++) {
        int j = __shfl_sync(0xffffffffu, myid, k);
        float4 v = *(const float4*)(base + (size_t)j * CIN);
        vmax.x = fmaxf(vmax.x, v.x);
        vmax.y = fmaxf(vmax.y, v.y);
        vmax.z = fmaxf(vmax.z, v.z);
        vmax.w = fmaxf(vmax.w, v.w);
    }

    float out[SEMOUT];
    #pragma unroll
    for (int o = 0; o < SEMOUT; o++) {
        float4 wv = *(const float4*)(W_sem + o * CIN + (lane << 2));
        float a = wv.x * vmax.x;
        a = fmaf(wv.y, vmax.y, a);
        a = fmaf(wv.z, vmax.z, a);
        a = fmaf(wv.w, vmax.w, a);
        a += __shfl_xor_sync(0xffffffffu, a, 16);
        a += __shfl_xor_sync(0xffffffffu, a, 8);
        a += __shfl_xor_sync(0xffffffffu, a, 4);
        a += __shfl_xor_sync(0xffffffffu, a, 2);
        a += __shfl_xor_sync(0xffffffffu, a, 1);
        out[o] = a;
    }
    if (lane == 0) {
        float* dst = p_out + ((size_t)b * SEMOUT) * NN + n;
        #pragma unroll
        for (int o = 0; o < SEMOUT; o++)
            dst[(size_t)o * NN] = out[o] + b_sem[o];
    }
}

// ================================================================
extern "C" void kernel_launch(void* const* d_in, const int* in_sizes, int n_in,
                              void* d_out, int out_size)
{
    (void)in_sizes; (void)n_in; (void)out_size;
    const float* f_sem   = (const float*)d_in[0];
    const float* f_ins   = (const float*)d_in[1];
    const float* W_adapt = (const float*)d_in[2];
    const float* b_adapt = (const float*)d_in[3];
    const float* gamma   = (const float*)d_in[4];
    const float* beta    = (const float*)d_in[5];
    const float* W_ins   = (const float*)d_in[6];
    const float* b_ins   = (const float*)d_in[7];
    const float* W_sem   = (const float*)d_in[8];
    const float* b_sem   = (const float*)d_in[9];

    float* p_out = (float*)d_out;                       // [B,13,N]
    float* e_out = p_out + (size_t)BB * SEMOUT * NN;    // [B,5,N]

    const int smem1 = (128 * XPAD + EOUT * 128 + 8) * 4;               // ~21KB
    const int smem2 = CHUNK * 24 + KSEL * KQT * 8 + QCAP * KQT * 8;    // 52KB

    cudaFuncSetAttribute(phase1_kernel,      cudaFuncAttributeMaxDynamicSharedMemorySize, smem1);
    cudaFuncSetAttribute(knn_partial_kernel, cudaFuncAttributeMaxDynamicSharedMemorySize, smem2);

    wt_kernel<<<CIN * CIN / 256, 256>>>(W_adapt);
    phase1_kernel<<<BB * (NN / TP), 128, smem1>>>(
        f_sem, f_ins, b_adapt, gamma, beta, W_ins, b_ins, e_out);
    knn_partial_kernel<<<BB * (NN / KQT) * NSLICE, KQT, smem2>>>();
    gather_kernel<<<BNN / 8, 256>>>(W_sem, b_sem, p_out);
}